// round 13
// baseline (speedup 1.0000x reference)
#include <cuda_runtime.h>
#include <math.h>
#include <stdint.h>

#define BB 2
#define NN 8192
#define KK 16

// ---------------- f32x2 packed-math helpers (sm_100+ PTX) ----------------
__device__ __forceinline__ unsigned long long ffma2(unsigned long long a, unsigned long long b,
                                                    unsigned long long c) {
    unsigned long long d;
    asm("fma.rn.f32x2 %0, %1, %2, %3;" : "=l"(d) : "l"(a), "l"(b), "l"(c));
    return d;
}
__device__ __forceinline__ unsigned long long pack2(float x, float y) {
    unsigned long long d;
    asm("mov.b64 %0, {%1, %2};" : "=l"(d) : "f"(x), "f"(y));
    return d;
}
__device__ __forceinline__ float2 unpack2(unsigned long long v) {
    float2 r;
    asm("mov.b64 {%0, %1}, %2;" : "=f"(r.x), "=f"(r.y) : "l"(v));
    return r;
}

// ---------------- scratch (static device globals; no allocation) ----------------
__device__ __align__(16) float4 g_cpack[BB*NN];   // raw coords + |c|^2
__device__ __align__(16) float4 g_cneg [BB*NN];   // (-2x,-2y,-2z, |c|^2) for KNN
__device__ __align__(16) int    g_idx [BB*NN*KK];
__device__ __align__(16) float  g_dist[BB*NN*KK];
__device__ __align__(16) float  g_y1   [BB*64 *NN];
__device__ __align__(16) float  g_pool1[BB*64 *NN];
__device__ __align__(16) float  g_y2   [BB*32 *NN];
__device__ __align__(16) float  g_pool2[BB*32 *NN];
__device__ __align__(16) float  g_ymain[BB*128*NN];
__device__ __align__(16) float  g_yres [BB*128*NN];
__device__ double g_msum[65];
__device__ double g_csum [352];   // [0,64)=mlp1 [64,96)=mlpp1 [96,224)=mlp2 [224,352)=res
__device__ double g_csum2[352];

// ---------------- pack coords + squared norm; zero accumulators ----------------
__global__ void __launch_bounds__(256) pack_kernel(const float* __restrict__ coords) {
    int p = (blockIdx.x << 8) + threadIdx.x;          // < BB*NN
    float x = coords[p*3+0], y = coords[p*3+1], z = coords[p*3+2];
    float w = fmaf(x, x, fmaf(y, y, z*z));
    g_cpack[p] = make_float4(x, y, z, w);
    g_cneg[p]  = make_float4(-2.f*x, -2.f*y, -2.f*z, w);
    if (p < 352) { g_csum[p] = 0.0; g_csum2[p] = 0.0; }
    if (p < 65)  g_msum[p] = 0.0;
}

// ---------------- KNN v6 (R10-proven): 4 queries/warp, queue + pivot-shrink ----------------
__device__ __forceinline__ float knn_exact16(float* qd, int* qi, float* td, int* ti,
                                             int lane, int& cnt) {
    const float INF = __int_as_float(0x7f800000);
    for (int s = cnt + lane; s < 128; s += 32) qd[s] = INF;
    __syncwarp();
    #pragma unroll 1
    for (int r = 0; r < 16; r++) {
        unsigned u  = __float_as_uint(qd[lane]);      int p = lane;
        unsigned u1 = __float_as_uint(qd[lane + 32]);
        unsigned u2 = __float_as_uint(qd[lane + 64]);
        unsigned u3 = __float_as_uint(qd[lane + 96]);
        if (u1 < u) { u = u1; p = lane + 32; }
        if (u2 < u) { u = u2; p = lane + 64; }
        if (u3 < u) { u = u3; p = lane + 96; }
        unsigned m  = __reduce_min_sync(0xffffffffu, u);
        unsigned z  = (u == m) ? (unsigned)p : 0xFFFFu;
        unsigned pm = __reduce_min_sync(0xffffffffu, z);
        if (lane == 0) {
            td[r] = __uint_as_float(m);
            ti[r] = qi[pm];
            qd[pm] = INF;
        }
        __syncwarp();
    }
    cnt = 0;
    __syncwarp();
    return td[15];
}

__device__ __forceinline__ float knn_shrink(float* qd, int* qi, float* td, int* ti,
                                            int lane, const unsigned lt, int& cnt) {
    const float INF = __int_as_float(0x7f800000);
    for (int s = cnt + lane; s < 128; s += 32) qd[s] = INF;
    __syncwarp();
    float v0 = qd[lane], v1 = qd[lane + 32], v2 = qd[lane + 64], v3 = qd[lane + 96];
    float mn = fminf(fminf(v0, v1), fminf(v2, v3));
    float mx = fmaxf(fmaxf(v0 < INF ? v0 : -INF, v1 < INF ? v1 : -INF),
                     fmaxf(v2 < INF ? v2 : -INF, v3 < INF ? v3 : -INF));
    #pragma unroll
    for (int off = 16; off; off >>= 1) {
        mn = fminf(mn, __shfl_xor_sync(0xffffffffu, mn, off));
        mx = fmaxf(mx, __shfl_xor_sync(0xffffffffu, mx, off));
    }
    float lo = mn, hi = mx;
    int hc = cnt;
    #pragma unroll 1
    for (int it = 0; it < 14 && hc > 64; it++) {
        float mid = 0.5f * (lo + hi);
        if (!(mid > lo) || !(mid < hi)) break;
        int c = (int)(v0 <= mid) + (int)(v1 <= mid) + (int)(v2 <= mid) + (int)(v3 <= mid);
        c = (int)__reduce_add_sync(0xffffffffu, (unsigned)c);
        if (c >= 16) { hi = mid; hc = c; } else lo = mid;
    }
    if (hc > 96) {                          // pathological duplicates: exact reset
        float tau = knn_exact16(qd, qi, td, ti, lane, cnt);
        if (lane < 16) { qd[lane] = td[lane]; qi[lane] = ti[lane]; }
        cnt = 16;
        __syncwarp();
        return tau;
    }
    int nc = 0;
    #pragma unroll
    for (int g = 0; g < 4; g++) {
        float v = (g == 0) ? v0 : (g == 1) ? v1 : (g == 2) ? v2 : v3;
        int idx = qi[lane + (g << 5)];
        bool keep = v <= hi;
        unsigned m = __ballot_sync(0xffffffffu, keep);
        if (keep) {
            int pos = nc + __popc(m & lt);
            qd[pos] = v;
            qi[pos] = idx;
        }
        nc += __popc(m);
    }
    cnt = nc;
    __syncwarp();
    return hi;
}

__global__ void __launch_bounds__(512, 2) knn_kernel() {
    extern __shared__ char dyn[];
    float4* tile = (float4*)dyn;                       // 1024*16 = 16384
    float*  qds  = (float*)(dyn + 16384);              // 64*128*4 = 32768
    int*    qis  = (int*)  (dyn + 49152);              // 32768
    float*  tds  = (float*)(dyn + 81920);              // 4096
    int*    tis  = (int*)  (dyn + 86016);              // 4096  (total 90112)

    const float INF = __int_as_float(0x7f800000);
    const int tid = threadIdx.x, w = tid >> 5, lane = tid & 31;
    const int b     = blockIdx.x >> 7;
    const int qbase = ((blockIdx.x & 127) << 6) | (w << 2);
    const int qslot = w << 2;
    const unsigned lt = (1u << lane) - 1u;

    float* qd0 = qds + ((qslot+0) << 7); int* qi0 = qis + ((qslot+0) << 7);
    float* qd1 = qds + ((qslot+1) << 7); int* qi1 = qis + ((qslot+1) << 7);
    float* qd2 = qds + ((qslot+2) << 7); int* qi2 = qis + ((qslot+2) << 7);
    float* qd3 = qds + ((qslot+3) << 7); int* qi3 = qis + ((qslot+3) << 7);
    float* td0 = tds + ((qslot+0) << 4); int* ti0 = tis + ((qslot+0) << 4);
    float* td1 = tds + ((qslot+1) << 4); int* ti1 = tis + ((qslot+1) << 4);
    float* td2 = tds + ((qslot+2) << 4); int* ti2 = tis + ((qslot+2) << 4);
    float* td3 = tds + ((qslot+3) << 4); int* ti3 = tis + ((qslot+3) << 4);

    const float4 q0 = g_cpack[(b << 13) + qbase + 0];
    const float4 q1 = g_cpack[(b << 13) + qbase + 1];
    const float4 q2 = g_cpack[(b << 13) + qbase + 2];
    const float4 q3 = g_cpack[(b << 13) + qbase + 3];
    const int n0 = qbase, n1 = qbase+1, n2 = qbase+2, n3 = qbase+3;
    float t0 = INF, t1 = INF, t2 = INF, t3 = INF;
    int c0 = 0, c1 = 0, c2 = 0, c3 = 0;

    for (int t = 0; t < 8; t++) {
        __syncthreads();
        tile[tid]       = g_cneg[(b << 13) + (t << 10) + tid];
        tile[tid + 512] = g_cneg[(b << 13) + (t << 10) + tid + 512];
        __syncthreads();
        const int jb = t << 10;
        #pragma unroll 1
        for (int s = 0; s < 32; s++) {
            float4 cc = tile[(s << 5) + lane];
            int j = jb + (s << 5) + lane;
            float e0 = fmaf(cc.x, q0.x, fmaf(cc.y, q0.y, fmaf(cc.z, q0.z, cc.w)));
            float e1 = fmaf(cc.x, q1.x, fmaf(cc.y, q1.y, fmaf(cc.z, q1.z, cc.w)));
            float e2 = fmaf(cc.x, q2.x, fmaf(cc.y, q2.y, fmaf(cc.z, q2.z, cc.w)));
            float e3 = fmaf(cc.x, q3.x, fmaf(cc.y, q3.y, fmaf(cc.z, q3.z, cc.w)));
            bool p0 = e0 < t0, p1 = e1 < t1, p2 = e2 < t2, p3 = e3 < t3;
            if (__ballot_sync(0xffffffffu, p0 | p1 | p2 | p3)) {
                unsigned m;
                #define KNN_PROC(P, E, QW, NQ, QD, QI, TD, TI, CN, TH)                      \
                    m = __ballot_sync(0xffffffffu, P);                                      \
                    if (m) {                                                                \
                        if (P) {                                                            \
                            int pos = CN + __popc(m & lt);                                  \
                            QD[pos] = (j == NQ) ? INF : fmaxf(E + QW, 0.f);                 \
                            QI[pos] = j;                                                    \
                        }                                                                   \
                        CN += __popc(m);                                                    \
                        if (CN > 96) TH = knn_shrink(QD, QI, TD, TI, lane, lt, CN) - QW;    \
                    }
                KNN_PROC(p0, e0, q0.w, n0, qd0, qi0, td0, ti0, c0, t0)
                KNN_PROC(p1, e1, q1.w, n1, qd1, qi1, td1, ti1, c1, t1)
                KNN_PROC(p2, e2, q2.w, n2, qd2, qi2, td2, ti2, c2, t2)
                KNN_PROC(p3, e3, q3.w, n3, qd3, qi3, td3, ti3, c3, t3)
                #undef KNN_PROC
            }
        }
    }
    knn_exact16(qd0, qi0, td0, ti0, lane, c0);
    knn_exact16(qd1, qi1, td1, ti1, lane, c1);
    knn_exact16(qd2, qi2, td2, ti2, lane, c2);
    knn_exact16(qd3, qi3, td3, ti3, lane, c3);

    if (lane < 16) {
        int base = ((b << 13) + qbase) << 4;
        g_idx [base + lane]      = ti0[lane];
        g_dist[base + lane]      = td0[lane];
        g_idx [base + 16 + lane] = ti1[lane];
        g_dist[base + 16 + lane] = td1[lane];
        g_idx [base + 32 + lane] = ti2[lane];
        g_dist[base + 32 + lane] = td2[lane];
        g_idx [base + 48 + lane] = ti3[lane];
        g_dist[base + 48 + lane] = td3[lane];
    }
}

// ---------------- spatial moments: 1 sample/thread, 1024 blocks (latency-parallel) --------
__global__ void __launch_bounds__(256) moments_kernel() {
    const int tid = threadIdx.x;
    const int p   = (blockIdx.x << 8) + tid;     // < BB*NN*KK = 262144 (grid = 1024)
    int bn = p >> 4;
    int b  = bn >> 13;
    int j  = g_idx[p];
    float d = g_dist[p];
    float4 ct = g_cpack[bn];
    float4 nb = g_cpack[(b << 13) + j];
    float s[10] = { ct.x, ct.y, ct.z, nb.x, nb.y, nb.z,
                    ct.x-nb.x, ct.y-nb.y, ct.z-nb.z, d };
    float a[65];
    int c2 = 10;
    #pragma unroll
    for (int i = 0; i < 10; i++) {
        a[i] = s[i];
        #pragma unroll
        for (int j2 = i; j2 < 10; j2++) { a[c2] = s[i]*s[j2]; c2++; }
    }
    __shared__ double sacc[65];
    if (tid < 65) sacc[tid] = 0.0;
    __syncthreads();
    #pragma unroll
    for (int v = 0; v < 65; v++) {
        float x = a[v];
        #pragma unroll
        for (int off = 16; off; off >>= 1) x += __shfl_down_sync(0xffffffffu, x, off);
        if ((tid & 31) == 0) atomicAdd(&sacc[v], (double)x);
    }
    __syncthreads();
    if (tid < 65) atomicAdd(&g_msum[tid], sacc[tid]);
}

// ---------------- fused conv A: features -> mlp1(64ch) + res(128ch), BN stats fused --------
__global__ void __launch_bounds__(256) convA_kernel(
    const float* __restrict__ feat,
    const float* __restrict__ w1, const float* __restrict__ b1,
    const float* __restrict__ w2, const float* __restrict__ b2,
    float* __restrict__ y1, float* __restrict__ yres) {
    __shared__ __align__(16) float Wsh[32*32];
    __shared__ float bsh[32];
    __shared__ float red_s[8][32], red_q[8][32];
    const int by = blockIdx.y;   // 0..5 : 0-1 -> mlp1, 2-5 -> res
    const float* W;  const float* bias;  float* y;  int oc0, CO, acc_off;
    if (by < 2) { W = w1; bias = b1; y = y1;   oc0 = by << 5;       CO = 64;  acc_off = 0; }
    else        { W = w2; bias = b2; y = yres; oc0 = (by - 2) << 5; CO = 128; acc_off = 224; }
    for (int t = threadIdx.x; t < 32*32; t += 256) {
        int i = t >> 5, ol = t & 31;
        Wsh[t] = W[(oc0 + ol)*32 + i];
    }
    if (threadIdx.x < 32) bsh[threadIdx.x] = bias[oc0 + threadIdx.x];
    __syncthreads();
    const int p = (blockIdx.x << 8) + threadIdx.x;
    const int b = p >> 13, n = p & (NN-1);
    const int w = threadIdx.x >> 5, lane = threadIdx.x & 31;
    unsigned long long acc2[16];
    #pragma unroll
    for (int o2 = 0; o2 < 16; o2++) acc2[o2] = pack2(bsh[2*o2], bsh[2*o2+1]);
    #pragma unroll 2
    for (int i = 0; i < 32; i++) {
        float x = feat[((b*32 + i) << 13) + n];
        unsigned long long x2 = pack2(x, x);
        const unsigned long long* wr = (const unsigned long long*)&Wsh[i << 5];
        #pragma unroll
        for (int o2 = 0; o2 < 16; o2++) acc2[o2] = ffma2(x2, wr[o2], acc2[o2]);
    }
    float acc[32];
    #pragma unroll
    for (int o2 = 0; o2 < 16; o2++) {
        float2 u = unpack2(acc2[o2]);
        acc[2*o2] = u.x; acc[2*o2+1] = u.y;
    }
    #pragma unroll
    for (int o = 0; o < 32; o++)
        y[((b*CO + oc0 + o) << 13) + n] = acc[o];
    #pragma unroll
    for (int o = 0; o < 32; o++) {
        float v = acc[o], q = v*v;
        #pragma unroll
        for (int off = 16; off; off >>= 1) {
            v += __shfl_xor_sync(0xffffffffu, v, off);
            q += __shfl_xor_sync(0xffffffffu, q, off);
        }
        if (lane == 0) { red_s[w][o] = v; red_q[w][o] = q; }
    }
    __syncthreads();
    if (threadIdx.x < 64) {
        int o = threadIdx.x & 31, which = threadIdx.x >> 5;
        float s = 0.f;
        #pragma unroll
        for (int ww = 0; ww < 8; ww++) s += which ? red_q[ww][o] : red_s[ww][o];
        atomicAdd(which ? &g_csum2[acc_off + oc0 + o] : &g_csum[acc_off + oc0 + o], (double)s);
    }
}

// ---------------- 1x1 conv (CI inputs), in1 gets in-place BN+act computed from g_csum -------
template<int CI, int CI0>
__global__ void __launch_bounds__(256) convB_kernel(
    const float* __restrict__ in0, const float* __restrict__ in1,
    const float* __restrict__ W,   const float* __restrict__ bias,
    const float* __restrict__ gprm, const float* __restrict__ btprm,
    int prm_off, float slope,
    float* __restrict__ y, int CO, int acc_off) {
    __shared__ __align__(16) float Wsh[CI*32];
    __shared__ float bsh[32];
    __shared__ float scsh[CI-CI0], shsh[CI-CI0];
    __shared__ float red_s[8][32], red_q[8][32];
    const int oc0 = blockIdx.y << 5;
    for (int t = threadIdx.x; t < CI*32; t += 256) {
        int i = t >> 5, ol = t & 31;
        Wsh[t] = W[(oc0 + ol)*CI + i];
    }
    if (threadIdx.x < 32) bsh[threadIdx.x] = bias[oc0 + threadIdx.x];
    if (threadIdx.x < (CI-CI0)) {
        int i = threadIdx.x;
        const double P = (double)(BB*NN);
        double mean = g_csum[prm_off + i] / P;
        double var  = g_csum2[prm_off + i] / P - mean*mean;
        double scl  = (double)gprm[i] / sqrt(var + 1e-5);
        scsh[i] = (float)scl;
        shsh[i] = (float)((double)btprm[i] - mean*scl);
    }
    __syncthreads();
    const int p = (blockIdx.x << 8) + threadIdx.x;
    const int b = p >> 13, n = p & (NN-1);
    const int w = threadIdx.x >> 5, lane = threadIdx.x & 31;
    unsigned long long acc2[16];
    #pragma unroll
    for (int o2 = 0; o2 < 16; o2++) acc2[o2] = pack2(bsh[2*o2], bsh[2*o2+1]);
    #pragma unroll 2
    for (int i = 0; i < CI0; i++) {
        float x = in0[((b*CI0 + i) << 13) + n];
        unsigned long long x2 = pack2(x, x);
        const unsigned long long* wr = (const unsigned long long*)&Wsh[i << 5];
        #pragma unroll
        for (int o2 = 0; o2 < 16; o2++) acc2[o2] = ffma2(x2, wr[o2], acc2[o2]);
    }
    #pragma unroll 2
    for (int i = 0; i < CI - CI0; i++) {
        float x = in1[((b*(CI-CI0) + i) << 13) + n];
        x = fmaf(x, scsh[i], shsh[i]);
        x = x > 0.f ? x : slope * x;
        unsigned long long x2 = pack2(x, x);
        const unsigned long long* wr = (const unsigned long long*)&Wsh[(CI0 + i) << 5];
        #pragma unroll
        for (int o2 = 0; o2 < 16; o2++) acc2[o2] = ffma2(x2, wr[o2], acc2[o2]);
    }
    float acc[32];
    #pragma unroll
    for (int o2 = 0; o2 < 16; o2++) {
        float2 u = unpack2(acc2[o2]);
        acc[2*o2] = u.x; acc[2*o2+1] = u.y;
    }
    #pragma unroll
    for (int o = 0; o < 32; o++)
        y[((b*CO + oc0 + o) << 13) + n] = acc[o];
    #pragma unroll
    for (int o = 0; o < 32; o++) {
        float v = acc[o], q = v*v;
        #pragma unroll
        for (int off = 16; off; off >>= 1) {
            v += __shfl_xor_sync(0xffffffffu, v, off);
            q += __shfl_xor_sync(0xffffffffu, q, off);
        }
        if (lane == 0) { red_s[w][o] = v; red_q[w][o] = q; }
    }
    __syncthreads();
    if (threadIdx.x < 64) {
        int o = threadIdx.x & 31, which = threadIdx.x >> 5;
        float s = 0.f;
        #pragma unroll
        for (int ww = 0; ww < 8; ww++) s += which ? red_q[ww][o] : red_s[ww][o];
        atomicAdd(which ? &g_csum2[acc_off + oc0 + o] : &g_csum[acc_off + oc0 + o], (double)s);
    }
}

// ---------------- fused LSE + attentive pool, PPW points/warp, BN-finalize in prologue -----
// h stored in smem pre-packed as f32x2 (u64) pairs; phase 4 re-reads from smem so hreg
// is dead after phase 2 (register pressure -> occupancy).
template<int C, int WARPS, int PPW>
__global__ void __launch_bounds__(WARPS*32) lse_pool_kernel(
    const float* __restrict__ Wl,  const float* __restrict__ bl,
    const float* __restrict__ lg,  const float* __restrict__ lbt,
    const float* __restrict__ Wp,  float* __restrict__ pooled) {
    constexpr int CPT = C / 32;
    constexpr int NT  = WARPS * 32;
    __shared__ float wl_sh[10 * C];
    __shared__ float wp_sh[C * C];
    __shared__ float prm_sh[3 * C];
    __shared__ float Cvs[10][10];
    __shared__ float mmf[10];
    __shared__ __align__(16) float s_sh[WARPS][16][12];
    __shared__ __align__(16) unsigned long long h_sh[WARPS][C][10];  // 8 used + pad

    const int tid = threadIdx.x;
    for (int t = tid; t < 10*C; t += NT) { int i = t / C, c = t % C; wl_sh[t] = Wl[c*10 + i]; }
    for (int t = tid; t < C*C;  t += NT) { int c = t / C, o = t % C; wp_sh[t] = Wp[o*(2*C) + c]; }
    const double P = (double)BB * NN * KK;
    if (tid < 10) mmf[tid] = (float)(g_msum[tid] / P);
    if (tid < 100) {
        int i = tid/10, j = tid%10;
        if (j >= i) {
            int off = 10 + i*10 - (i*(i-1))/2 + (j - i);
            float c = (float)(g_msum[off]/P - (g_msum[i]/P)*(g_msum[j]/P));
            Cvs[i][j] = c; Cvs[j][i] = c;
        }
    }
    __syncthreads();
    if (tid < C) {
        int o = tid;
        float wv[10];
        #pragma unroll
        for (int i = 0; i < 10; i++) wv[i] = wl_sh[i*C + o];
        float mean = bl[o];
        #pragma unroll
        for (int i = 0; i < 10; i++) mean = fmaf(wv[i], mmf[i], mean);
        float var = 0.f;
        #pragma unroll
        for (int i = 0; i < 10; i++) {
            float t = 0.f;
            #pragma unroll
            for (int j = 0; j < 10; j++) t = fmaf(wv[j], Cvs[i][j], t);
            var = fmaf(wv[i], t, var);
        }
        float scl = lg[o] / sqrtf(var + 1e-5f);
        prm_sh[o]       = bl[o];
        prm_sh[C + o]   = scl;
        prm_sh[2*C + o] = lbt[o] - mean*scl;
    }
    __syncthreads();

    const int w = tid >> 5, lane = tid & 31;

    float wlr[CPT][10], br[CPT], scr[CPT], shr[CPT];
    #pragma unroll
    for (int cc = 0; cc < CPT; cc++) {
        int c = lane + 32*cc;
        #pragma unroll
        for (int i = 0; i < 10; i++) wlr[cc][i] = wl_sh[i*C + c];
        br[cc] = prm_sh[c]; scr[cc] = prm_sh[C + c]; shr[cc] = prm_sh[2*C + c];
    }

    #pragma unroll 1
    for (int pp = 0; pp < PPW; pp++) {
        const int pt = (blockIdx.x * WARPS + w) * PPW + pp;
        const int b  = pt >> 13;
        const int n  = pt & (NN-1);

        if (lane < 16) {
            int gofs = (pt << 4) | lane;
            int j    = g_idx[gofs];
            float d  = g_dist[gofs];
            float4 ct = g_cpack[pt];
            float4 nb = g_cpack[(b << 13) + j];
            float* sr = s_sh[w][lane];
            sr[0]=ct.x; sr[1]=ct.y; sr[2]=ct.z;
            sr[3]=nb.x; sr[4]=nb.y; sr[5]=nb.z;
            sr[6]=ct.x-nb.x; sr[7]=ct.y-nb.y; sr[8]=ct.z-nb.z;
            sr[9]=d; sr[10]=0.f; sr[11]=0.f;
        }
        __syncwarp();

        // phase 2: h in registers (scoped), store pre-packed u64 pairs
        {
            float hreg[CPT][16];
            #pragma unroll
            for (int k = 0; k < 16; k++) {
                const float4* sp = (const float4*)s_sh[w][k];
                float4 a0 = sp[0], a1 = sp[1], a2 = sp[2];
                float sv[10] = { a0.x,a0.y,a0.z,a0.w, a1.x,a1.y,a1.z,a1.w, a2.x,a2.y };
                #pragma unroll
                for (int cc = 0; cc < CPT; cc++) {
                    float yv = br[cc];
                    #pragma unroll
                    for (int i = 0; i < 10; i++) yv = fmaf(wlr[cc][i], sv[i], yv);
                    hreg[cc][k] = fmaxf(fmaf(yv, scr[cc], shr[cc]), 0.f);
                }
            }
            #pragma unroll
            for (int cc = 0; cc < CPT; cc++) {
                ulonglong2* dst = (ulonglong2*)&h_sh[w][lane + 32*cc][0];
                dst[0] = make_ulonglong2(pack2(hreg[cc][0],  hreg[cc][1]),
                                         pack2(hreg[cc][2],  hreg[cc][3]));
                dst[1] = make_ulonglong2(pack2(hreg[cc][4],  hreg[cc][5]),
                                         pack2(hreg[cc][6],  hreg[cc][7]));
                dst[2] = make_ulonglong2(pack2(hreg[cc][8],  hreg[cc][9]),
                                         pack2(hreg[cc][10], hreg[cc][11]));
                dst[3] = make_ulonglong2(pack2(hreg[cc][12], hreg[cc][13]),
                                         pack2(hreg[cc][14], hreg[cc][15]));
            }
        }
        __syncwarp();

        // phase 3: score GEMM, packed operands straight from smem
        unsigned long long acc2[CPT][8];
        #pragma unroll
        for (int cc = 0; cc < CPT; cc++)
            #pragma unroll
            for (int k2 = 0; k2 < 8; k2++) acc2[cc][k2] = 0ULL;

        #pragma unroll 4
        for (int c = 0; c < C; c++) {
            const ulonglong2* hp = (const ulonglong2*)&h_sh[w][c][0];
            ulonglong2 A = hp[0], Bq = hp[1], Cq = hp[2], D = hp[3];
            unsigned long long hv2[8] = { A.x, A.y, Bq.x, Bq.y, Cq.x, Cq.y, D.x, D.y };
            #pragma unroll
            for (int cc = 0; cc < CPT; cc++) {
                float wv = wp_sh[c*C + lane + 32*cc];
                unsigned long long w2 = pack2(wv, wv);
                #pragma unroll
                for (int k2 = 0; k2 < 8; k2++) acc2[cc][k2] = ffma2(w2, hv2[k2], acc2[cc][k2]);
            }
        }

        // phase 4: softmax over K + weighted sum (h re-read from smem)
        #pragma unroll
        for (int cc = 0; cc < CPT; cc++) {
            int o = lane + 32*cc;
            float acc[16];
            #pragma unroll
            for (int k2 = 0; k2 < 8; k2++) {
                float2 u = unpack2(acc2[cc][k2]);
                acc[2*k2] = u.x; acc[2*k2+1] = u.y;
            }
            float m = acc[0];
            #pragma unroll
            for (int k = 1; k < 16; k++) m = fmaxf(m, acc[k]);
            float se = 0.f;
            #pragma unroll
            for (int k = 0; k < 16; k++) { acc[k] = __expf(acc[k] - m); se += acc[k]; }
            const float4* hp = (const float4*)&h_sh[w][o][0];
            float4 h0 = hp[0], h1 = hp[1], h2 = hp[2], h3 = hp[3];
            float hv[16] = { h0.x,h0.y,h0.z,h0.w, h1.x,h1.y,h1.z,h1.w,
                             h2.x,h2.y,h2.z,h2.w, h3.x,h3.y,h3.z,h3.w };
            float sum = 0.f;
            #pragma unroll
            for (int k = 0; k < 16; k++) sum = fmaf(acc[k], hv[k], sum);
            pooled[((b*C + o) << 13) + n] = sum / se;
        }
        __syncwarp();
    }
}

// ---------------- final: BN params in-block, BN+ReLU+concat, grid-stride float4 ----
__global__ void __launch_bounds__(256) final_kernel(
    const float* __restrict__ gm, const float* __restrict__ btm,
    const float* __restrict__ gr, const float* __restrict__ btr,
    float4* __restrict__ out) {
    __shared__ float scm[128], shm[128], scr_[128], shr_[128];
    const double P = (double)(BB*NN);
    {
        int t = threadIdx.x;
        int off = (t < 128) ? 96 : 224;
        int o   = t & 127;
        double mean = g_csum[off + o] / P;
        double var  = g_csum2[off + o] / P - mean*mean;
        const float* gg = (t < 128) ? gm : gr;
        const float* bb = (t < 128) ? btm : btr;
        double scl = (double)gg[o] / sqrt(var + 1e-5);
        if (t < 128) { scm[o] = (float)scl; shm[o] = (float)((double)bb[o] - mean*scl); }
        else         { scr_[o] = (float)scl; shr_[o] = (float)((double)bb[o] - mean*scl); }
    }
    __syncthreads();
    const int total = BB*256*NN/4;
    for (int t = (blockIdx.x << 8) + threadIdx.x; t < total; t += 1024*256) {
        int base = t << 2;
        int b  = base >> 21;
        int r  = base & ((1 << 21) - 1);
        int ch = r >> 13;
        int n  = r & (NN-1);
        float4 v; float sc, sh;
        if (ch < 128) {
            v = *(const float4*)&g_ymain[((b*128 + ch) << 13) + n];
            sc = scm[ch]; sh = shm[ch];
        } else {
            int c = ch - 128;
            v = *(const float4*)&g_yres[((b*128 + c) << 13) + n];
            sc = scr_[c]; sh = shr_[c];
        }
        v.x = fmaxf(fmaf(v.x, sc, sh), 0.f);
        v.y = fmaxf(fmaf(v.y, sc, sh), 0.f);
        v.z = fmaxf(fmaf(v.z, sc, sh), 0.f);
        v.w = fmaxf(fmaf(v.w, sc, sh), 0.f);
        out[t] = v;
    }
}

// ---------------- launch ----------------
extern "C" void kernel_launch(void* const* d_in, const int* in_sizes, int n_in,
                              void* d_out, int out_size) {
    const float* coords   = (const float*)d_in[0];
    const float* features = (const float*)d_in[1];
    const float* mlp1_w  = (const float*)d_in[2];
    const float* mlp1_b  = (const float*)d_in[3];
    const float* mlp1_g  = (const float*)d_in[4];
    const float* mlp1_bt = (const float*)d_in[5];
    const float* lse1_w  = (const float*)d_in[6];
    const float* lse1_b  = (const float*)d_in[7];
    const float* lse1_g  = (const float*)d_in[8];
    const float* lse1_bt = (const float*)d_in[9];
    const float* mlpp1_w  = (const float*)d_in[10];
    const float* mlpp1_b  = (const float*)d_in[11];
    const float* mlpp1_g  = (const float*)d_in[12];
    const float* mlpp1_bt = (const float*)d_in[13];
    const float* lse2_w  = (const float*)d_in[14];
    const float* lse2_b  = (const float*)d_in[15];
    const float* lse2_g  = (const float*)d_in[16];
    const float* lse2_bt = (const float*)d_in[17];
    const float* mlp2_w  = (const float*)d_in[18];
    const float* mlp2_b  = (const float*)d_in[19];
    const float* mlp2_g  = (const float*)d_in[20];
    const float* mlp2_bt = (const float*)d_in[21];
    const float* res_w  = (const float*)d_in[22];
    const float* res_b  = (const float*)d_in[23];
    const float* res_g  = (const float*)d_in[24];
    const float* res_bt = (const float*)d_in[25];
    const float* pool1_w = (const float*)d_in[26];
    const float* pool2_w = (const float*)d_in[28];
    float* out = (float*)d_out;

    void *p_y1, *p_pool1, *p_y2, *p_pool2, *p_ymain, *p_yres;
    cudaGetSymbolAddress(&p_y1, g_y1);       cudaGetSymbolAddress(&p_pool1, g_pool1);
    cudaGetSymbolAddress(&p_y2, g_y2);       cudaGetSymbolAddress(&p_pool2, g_pool2);
    cudaGetSymbolAddress(&p_ymain, g_ymain); cudaGetSymbolAddress(&p_yres, g_yres);

    static bool attr_done = false;
    if (!attr_done) {
        cudaFuncSetAttribute(knn_kernel, cudaFuncAttributeMaxDynamicSharedMemorySize, 90112);
        attr_done = true;
    }

    // 1) pack (zeros accumulators)
    pack_kernel<<<64, 256>>>(coords);
    // 2) fused conv: mlp1 + res from features
    convA_kernel<<<dim3(64,6), 256>>>(features, mlp1_w, mlp1_b, res_w, res_b,
                                      (float*)p_y1, (float*)p_yres);
    // 3) knn
    knn_kernel<<<256, 512, 90112>>>();
    // 4) spatial moments (1 sample/thread, 1024*256 = 262144 = BB*NN*KK)
    moments_kernel<<<1024, 256>>>();
    // 5) lse1 + pool1 (PPW=8)
    lse_pool_kernel<64,4,8><<<512, 128>>>(lse1_w, lse1_b, lse1_g, lse1_bt,
                                          pool1_w, (float*)p_pool1);
    // 6) mlpp1
    convB_kernel<128,64><<<dim3(64,1), 256>>>((float*)p_pool1, (float*)p_y1, mlpp1_w, mlpp1_b,
                                              mlp1_g, mlp1_bt, 0, 0.2f, (float*)p_y2, 32, 64);
    // 7) lse2 + pool2 (PPW=8)
    lse_pool_kernel<32,8,8><<<256, 256>>>(lse2_w, lse2_b, lse2_g, lse2_bt,
                                          pool2_w, (float*)p_pool2);
    // 8) mlp2
    convB_kernel<64,32><<<dim3(64,4), 256>>>((float*)p_pool2, (float*)p_y2, mlp2_w, mlp2_b,
                                             mlpp1_g, mlpp1_bt, 64, 0.0f, (float*)p_ymain, 128, 96);
    // 9) final
    final_kernel<<<1024, 256>>>(mlp2_g, mlp2_bt, res_g, res_bt, (float4*)out);
}

// round 14
// speedup vs baseline: 1.1412x; 1.1412x over previous
#include <cuda_runtime.h>
#include <math.h>
#include <stdint.h>

#define BB 2
#define NN 8192
#define KK 16

// ---------------- f32x2 packed-math helpers (sm_100+ PTX) ----------------
__device__ __forceinline__ unsigned long long ffma2(unsigned long long a, unsigned long long b,
                                                    unsigned long long c) {
    unsigned long long d;
    asm("fma.rn.f32x2 %0, %1, %2, %3;" : "=l"(d) : "l"(a), "l"(b), "l"(c));
    return d;
}
__device__ __forceinline__ unsigned long long pack2(float x, float y) {
    unsigned long long d;
    asm("mov.b64 %0, {%1, %2};" : "=l"(d) : "f"(x), "f"(y));
    return d;
}
__device__ __forceinline__ float2 unpack2(unsigned long long v) {
    float2 r;
    asm("mov.b64 {%0, %1}, %2;" : "=f"(r.x), "=f"(r.y) : "l"(v));
    return r;
}

// ---------------- scratch (static device globals; no allocation) ----------------
__device__ __align__(16) float4 g_cpack[BB*NN];   // raw coords + |c|^2
__device__ __align__(16) float4 g_cneg [BB*NN];   // (-2x,-2y,-2z, |c|^2) for KNN
__device__ __align__(16) int    g_idx [BB*NN*KK];
__device__ __align__(16) float  g_dist[BB*NN*KK];
__device__ __align__(16) float  g_y1   [BB*64 *NN];
__device__ __align__(16) float  g_pool1[BB*64 *NN];
__device__ __align__(16) float  g_y2   [BB*32 *NN];
__device__ __align__(16) float  g_pool2[BB*32 *NN];
__device__ __align__(16) float  g_ymain[BB*128*NN];
__device__ __align__(16) float  g_yres [BB*128*NN];
__device__ double g_msum[65];
__device__ double g_csum [352];   // [0,64)=mlp1 [64,96)=mlpp1 [96,224)=mlp2 [224,352)=res
__device__ double g_csum2[352];

// ---------------- pack coords + squared norm; zero accumulators ----------------
__global__ void __launch_bounds__(256) pack_kernel(const float* __restrict__ coords) {
    int p = (blockIdx.x << 8) + threadIdx.x;          // < BB*NN
    float x = coords[p*3+0], y = coords[p*3+1], z = coords[p*3+2];
    float w = fmaf(x, x, fmaf(y, y, z*z));
    g_cpack[p] = make_float4(x, y, z, w);
    g_cneg[p]  = make_float4(-2.f*x, -2.f*y, -2.f*z, w);
    if (p < 352) { g_csum[p] = 0.0; g_csum2[p] = 0.0; }
    if (p < 65)  g_msum[p] = 0.0;
}

// ---------------- KNN v6 (R10-proven): 4 queries/warp, queue + pivot-shrink ----------------
__device__ __forceinline__ float knn_exact16(float* qd, int* qi, float* td, int* ti,
                                             int lane, int& cnt) {
    const float INF = __int_as_float(0x7f800000);
    for (int s = cnt + lane; s < 128; s += 32) qd[s] = INF;
    __syncwarp();
    #pragma unroll 1
    for (int r = 0; r < 16; r++) {
        unsigned u  = __float_as_uint(qd[lane]);      int p = lane;
        unsigned u1 = __float_as_uint(qd[lane + 32]);
        unsigned u2 = __float_as_uint(qd[lane + 64]);
        unsigned u3 = __float_as_uint(qd[lane + 96]);
        if (u1 < u) { u = u1; p = lane + 32; }
        if (u2 < u) { u = u2; p = lane + 64; }
        if (u3 < u) { u = u3; p = lane + 96; }
        unsigned m  = __reduce_min_sync(0xffffffffu, u);
        unsigned z  = (u == m) ? (unsigned)p : 0xFFFFu;
        unsigned pm = __reduce_min_sync(0xffffffffu, z);
        if (lane == 0) {
            td[r] = __uint_as_float(m);
            ti[r] = qi[pm];
            qd[pm] = INF;
        }
        __syncwarp();
    }
    cnt = 0;
    __syncwarp();
    return td[15];
}

__device__ __forceinline__ float knn_shrink(float* qd, int* qi, float* td, int* ti,
                                            int lane, const unsigned lt, int& cnt) {
    const float INF = __int_as_float(0x7f800000);
    for (int s = cnt + lane; s < 128; s += 32) qd[s] = INF;
    __syncwarp();
    float v0 = qd[lane], v1 = qd[lane + 32], v2 = qd[lane + 64], v3 = qd[lane + 96];
    float mn = fminf(fminf(v0, v1), fminf(v2, v3));
    float mx = fmaxf(fmaxf(v0 < INF ? v0 : -INF, v1 < INF ? v1 : -INF),
                     fmaxf(v2 < INF ? v2 : -INF, v3 < INF ? v3 : -INF));
    #pragma unroll
    for (int off = 16; off; off >>= 1) {
        mn = fminf(mn, __shfl_xor_sync(0xffffffffu, mn, off));
        mx = fmaxf(mx, __shfl_xor_sync(0xffffffffu, mx, off));
    }
    float lo = mn, hi = mx;
    int hc = cnt;
    #pragma unroll 1
    for (int it = 0; it < 14 && hc > 64; it++) {
        float mid = 0.5f * (lo + hi);
        if (!(mid > lo) || !(mid < hi)) break;
        int c = (int)(v0 <= mid) + (int)(v1 <= mid) + (int)(v2 <= mid) + (int)(v3 <= mid);
        c = (int)__reduce_add_sync(0xffffffffu, (unsigned)c);
        if (c >= 16) { hi = mid; hc = c; } else lo = mid;
    }
    if (hc > 96) {                          // pathological duplicates: exact reset
        float tau = knn_exact16(qd, qi, td, ti, lane, cnt);
        if (lane < 16) { qd[lane] = td[lane]; qi[lane] = ti[lane]; }
        cnt = 16;
        __syncwarp();
        return tau;
    }
    int nc = 0;
    #pragma unroll
    for (int g = 0; g < 4; g++) {
        float v = (g == 0) ? v0 : (g == 1) ? v1 : (g == 2) ? v2 : v3;
        int idx = qi[lane + (g << 5)];
        bool keep = v <= hi;
        unsigned m = __ballot_sync(0xffffffffu, keep);
        if (keep) {
            int pos = nc + __popc(m & lt);
            qd[pos] = v;
            qi[pos] = idx;
        }
        nc += __popc(m);
    }
    cnt = nc;
    __syncwarp();
    return hi;
}

__global__ void __launch_bounds__(512, 2) knn_kernel() {
    extern __shared__ char dyn[];
    float4* tile = (float4*)dyn;                       // 1024*16 = 16384
    float*  qds  = (float*)(dyn + 16384);              // 64*128*4 = 32768
    int*    qis  = (int*)  (dyn + 49152);              // 32768
    float*  tds  = (float*)(dyn + 81920);              // 4096
    int*    tis  = (int*)  (dyn + 86016);              // 4096  (total 90112)

    const float INF = __int_as_float(0x7f800000);
    const int tid = threadIdx.x, w = tid >> 5, lane = tid & 31;
    const int b     = blockIdx.x >> 7;
    const int qbase = ((blockIdx.x & 127) << 6) | (w << 2);
    const int qslot = w << 2;
    const unsigned lt = (1u << lane) - 1u;

    float* qd0 = qds + ((qslot+0) << 7); int* qi0 = qis + ((qslot+0) << 7);
    float* qd1 = qds + ((qslot+1) << 7); int* qi1 = qis + ((qslot+1) << 7);
    float* qd2 = qds + ((qslot+2) << 7); int* qi2 = qis + ((qslot+2) << 7);
    float* qd3 = qds + ((qslot+3) << 7); int* qi3 = qis + ((qslot+3) << 7);
    float* td0 = tds + ((qslot+0) << 4); int* ti0 = tis + ((qslot+0) << 4);
    float* td1 = tds + ((qslot+1) << 4); int* ti1 = tis + ((qslot+1) << 4);
    float* td2 = tds + ((qslot+2) << 4); int* ti2 = tis + ((qslot+2) << 4);
    float* td3 = tds + ((qslot+3) << 4); int* ti3 = tis + ((qslot+3) << 4);

    const float4 q0 = g_cpack[(b << 13) + qbase + 0];
    const float4 q1 = g_cpack[(b << 13) + qbase + 1];
    const float4 q2 = g_cpack[(b << 13) + qbase + 2];
    const float4 q3 = g_cpack[(b << 13) + qbase + 3];
    const int n0 = qbase, n1 = qbase+1, n2 = qbase+2, n3 = qbase+3;
    float t0 = INF, t1 = INF, t2 = INF, t3 = INF;
    int c0 = 0, c1 = 0, c2 = 0, c3 = 0;

    for (int t = 0; t < 8; t++) {
        __syncthreads();
        tile[tid]       = g_cneg[(b << 13) + (t << 10) + tid];
        tile[tid + 512] = g_cneg[(b << 13) + (t << 10) + tid + 512];
        __syncthreads();
        const int jb = t << 10;
        #pragma unroll 1
        for (int s = 0; s < 32; s++) {
            float4 cc = tile[(s << 5) + lane];
            int j = jb + (s << 5) + lane;
            float e0 = fmaf(cc.x, q0.x, fmaf(cc.y, q0.y, fmaf(cc.z, q0.z, cc.w)));
            float e1 = fmaf(cc.x, q1.x, fmaf(cc.y, q1.y, fmaf(cc.z, q1.z, cc.w)));
            float e2 = fmaf(cc.x, q2.x, fmaf(cc.y, q2.y, fmaf(cc.z, q2.z, cc.w)));
            float e3 = fmaf(cc.x, q3.x, fmaf(cc.y, q3.y, fmaf(cc.z, q3.z, cc.w)));
            bool p0 = e0 < t0, p1 = e1 < t1, p2 = e2 < t2, p3 = e3 < t3;
            if (__ballot_sync(0xffffffffu, p0 | p1 | p2 | p3)) {
                unsigned m;
                #define KNN_PROC(P, E, QW, NQ, QD, QI, TD, TI, CN, TH)                      \
                    m = __ballot_sync(0xffffffffu, P);                                      \
                    if (m) {                                                                \
                        if (P) {                                                            \
                            int pos = CN + __popc(m & lt);                                  \
                            QD[pos] = (j == NQ) ? INF : fmaxf(E + QW, 0.f);                 \
                            QI[pos] = j;                                                    \
                        }                                                                   \
                        CN += __popc(m);                                                    \
                        if (CN > 96) TH = knn_shrink(QD, QI, TD, TI, lane, lt, CN) - QW;    \
                    }
                KNN_PROC(p0, e0, q0.w, n0, qd0, qi0, td0, ti0, c0, t0)
                KNN_PROC(p1, e1, q1.w, n1, qd1, qi1, td1, ti1, c1, t1)
                KNN_PROC(p2, e2, q2.w, n2, qd2, qi2, td2, ti2, c2, t2)
                KNN_PROC(p3, e3, q3.w, n3, qd3, qi3, td3, ti3, c3, t3)
                #undef KNN_PROC
            }
        }
    }
    knn_exact16(qd0, qi0, td0, ti0, lane, c0);
    knn_exact16(qd1, qi1, td1, ti1, lane, c1);
    knn_exact16(qd2, qi2, td2, ti2, lane, c2);
    knn_exact16(qd3, qi3, td3, ti3, lane, c3);

    if (lane < 16) {
        int base = ((b << 13) + qbase) << 4;
        g_idx [base + lane]      = ti0[lane];
        g_dist[base + lane]      = td0[lane];
        g_idx [base + 16 + lane] = ti1[lane];
        g_dist[base + 16 + lane] = td1[lane];
        g_idx [base + 32 + lane] = ti2[lane];
        g_dist[base + 32 + lane] = td2[lane];
        g_idx [base + 48 + lane] = ti3[lane];
        g_dist[base + 48 + lane] = td3[lane];
    }
}

// ---------------- spatial moments: 4 samples/thread, 128thr x 512 blocks -------------------
__global__ void __launch_bounds__(128) moments_kernel() {
    const int tid = threadIdx.x;
    float a[65];
    #pragma unroll
    for (int v = 0; v < 65; v++) a[v] = 0.f;
    const int p0 = (((blockIdx.x << 7) + tid) << 2);   // grid 512: covers BB*NN*KK
    for (int q = 0; q < 4; q++) {
        int p  = p0 + q;
        int bn = p >> 4;
        int b  = bn >> 13;
        int j  = g_idx[p];
        float d = g_dist[p];
        float4 ct = g_cpack[bn];
        float4 nb = g_cpack[(b << 13) + j];
        float s[10] = { ct.x, ct.y, ct.z, nb.x, nb.y, nb.z,
                        ct.x-nb.x, ct.y-nb.y, ct.z-nb.z, d };
        int c2 = 10;
        #pragma unroll
        for (int i = 0; i < 10; i++) {
            a[i] += s[i];
            #pragma unroll
            for (int j2 = i; j2 < 10; j2++) { a[c2] = fmaf(s[i], s[j2], a[c2]); c2++; }
        }
    }
    __shared__ double sacc[65];
    if (tid < 65) sacc[tid] = 0.0;
    __syncthreads();
    #pragma unroll
    for (int v = 0; v < 65; v++) {
        float x = a[v];
        #pragma unroll
        for (int off = 16; off; off >>= 1) x += __shfl_down_sync(0xffffffffu, x, off);
        if ((tid & 31) == 0) atomicAdd(&sacc[v], (double)x);
    }
    __syncthreads();
    if (tid < 65) atomicAdd(&g_msum[tid], sacc[tid]);
}

// ---------------- fused conv A: features -> mlp1(64ch) + res(128ch), BN stats fused --------
__global__ void __launch_bounds__(256) convA_kernel(
    const float* __restrict__ feat,
    const float* __restrict__ w1, const float* __restrict__ b1,
    const float* __restrict__ w2, const float* __restrict__ b2,
    float* __restrict__ y1, float* __restrict__ yres) {
    __shared__ __align__(16) float Wsh[32*32];
    __shared__ float bsh[32];
    __shared__ float red_s[8][32], red_q[8][32];
    const int by = blockIdx.y;   // 0..5 : 0-1 -> mlp1, 2-5 -> res
    const float* W;  const float* bias;  float* y;  int oc0, CO, acc_off;
    if (by < 2) { W = w1; bias = b1; y = y1;   oc0 = by << 5;       CO = 64;  acc_off = 0; }
    else        { W = w2; bias = b2; y = yres; oc0 = (by - 2) << 5; CO = 128; acc_off = 224; }
    for (int t = threadIdx.x; t < 32*32; t += 256) {
        int i = t >> 5, ol = t & 31;
        Wsh[t] = W[(oc0 + ol)*32 + i];
    }
    if (threadIdx.x < 32) bsh[threadIdx.x] = bias[oc0 + threadIdx.x];
    __syncthreads();
    const int p = (blockIdx.x << 8) + threadIdx.x;
    const int b = p >> 13, n = p & (NN-1);
    const int w = threadIdx.x >> 5, lane = threadIdx.x & 31;
    unsigned long long acc2[16];
    #pragma unroll
    for (int o2 = 0; o2 < 16; o2++) acc2[o2] = pack2(bsh[2*o2], bsh[2*o2+1]);
    #pragma unroll 2
    for (int i = 0; i < 32; i++) {
        float x = feat[((b*32 + i) << 13) + n];
        unsigned long long x2 = pack2(x, x);
        const unsigned long long* wr = (const unsigned long long*)&Wsh[i << 5];
        #pragma unroll
        for (int o2 = 0; o2 < 16; o2++) acc2[o2] = ffma2(x2, wr[o2], acc2[o2]);
    }
    float acc[32];
    #pragma unroll
    for (int o2 = 0; o2 < 16; o2++) {
        float2 u = unpack2(acc2[o2]);
        acc[2*o2] = u.x; acc[2*o2+1] = u.y;
    }
    #pragma unroll
    for (int o = 0; o < 32; o++)
        y[((b*CO + oc0 + o) << 13) + n] = acc[o];
    #pragma unroll
    for (int o = 0; o < 32; o++) {
        float v = acc[o], q = v*v;
        #pragma unroll
        for (int off = 16; off; off >>= 1) {
            v += __shfl_xor_sync(0xffffffffu, v, off);
            q += __shfl_xor_sync(0xffffffffu, q, off);
        }
        if (lane == 0) { red_s[w][o] = v; red_q[w][o] = q; }
    }
    __syncthreads();
    if (threadIdx.x < 64) {
        int o = threadIdx.x & 31, which = threadIdx.x >> 5;
        float s = 0.f;
        #pragma unroll
        for (int ww = 0; ww < 8; ww++) s += which ? red_q[ww][o] : red_s[ww][o];
        atomicAdd(which ? &g_csum2[acc_off + oc0 + o] : &g_csum[acc_off + oc0 + o], (double)s);
    }
}

// ---------------- 1x1 conv (CI inputs), in1 gets in-place BN+act computed from g_csum -------
template<int CI, int CI0>
__global__ void __launch_bounds__(256) convB_kernel(
    const float* __restrict__ in0, const float* __restrict__ in1,
    const float* __restrict__ W,   const float* __restrict__ bias,
    const float* __restrict__ gprm, const float* __restrict__ btprm,
    int prm_off, float slope,
    float* __restrict__ y, int CO, int acc_off) {
    __shared__ __align__(16) float Wsh[CI*32];
    __shared__ float bsh[32];
    __shared__ float scsh[CI-CI0], shsh[CI-CI0];
    __shared__ float red_s[8][32], red_q[8][32];
    const int oc0 = blockIdx.y << 5;
    for (int t = threadIdx.x; t < CI*32; t += 256) {
        int i = t >> 5, ol = t & 31;
        Wsh[t] = W[(oc0 + ol)*CI + i];
    }
    if (threadIdx.x < 32) bsh[threadIdx.x] = bias[oc0 + threadIdx.x];
    if (threadIdx.x < (CI-CI0)) {
        int i = threadIdx.x;
        const double P = (double)(BB*NN);
        double mean = g_csum[prm_off + i] / P;
        double var  = g_csum2[prm_off + i] / P - mean*mean;
        double scl  = (double)gprm[i] / sqrt(var + 1e-5);
        scsh[i] = (float)scl;
        shsh[i] = (float)((double)btprm[i] - mean*scl);
    }
    __syncthreads();
    const int p = (blockIdx.x << 8) + threadIdx.x;
    const int b = p >> 13, n = p & (NN-1);
    const int w = threadIdx.x >> 5, lane = threadIdx.x & 31;
    unsigned long long acc2[16];
    #pragma unroll
    for (int o2 = 0; o2 < 16; o2++) acc2[o2] = pack2(bsh[2*o2], bsh[2*o2+1]);
    #pragma unroll 2
    for (int i = 0; i < CI0; i++) {
        float x = in0[((b*CI0 + i) << 13) + n];
        unsigned long long x2 = pack2(x, x);
        const unsigned long long* wr = (const unsigned long long*)&Wsh[i << 5];
        #pragma unroll
        for (int o2 = 0; o2 < 16; o2++) acc2[o2] = ffma2(x2, wr[o2], acc2[o2]);
    }
    #pragma unroll 2
    for (int i = 0; i < CI - CI0; i++) {
        float x = in1[((b*(CI-CI0) + i) << 13) + n];
        x = fmaf(x, scsh[i], shsh[i]);
        x = x > 0.f ? x : slope * x;
        unsigned long long x2 = pack2(x, x);
        const unsigned long long* wr = (const unsigned long long*)&Wsh[(CI0 + i) << 5];
        #pragma unroll
        for (int o2 = 0; o2 < 16; o2++) acc2[o2] = ffma2(x2, wr[o2], acc2[o2]);
    }
    float acc[32];
    #pragma unroll
    for (int o2 = 0; o2 < 16; o2++) {
        float2 u = unpack2(acc2[o2]);
        acc[2*o2] = u.x; acc[2*o2+1] = u.y;
    }
    #pragma unroll
    for (int o = 0; o < 32; o++)
        y[((b*CO + oc0 + o) << 13) + n] = acc[o];
    #pragma unroll
    for (int o = 0; o < 32; o++) {
        float v = acc[o], q = v*v;
        #pragma unroll
        for (int off = 16; off; off >>= 1) {
            v += __shfl_xor_sync(0xffffffffu, v, off);
            q += __shfl_xor_sync(0xffffffffu, q, off);
        }
        if (lane == 0) { red_s[w][o] = v; red_q[w][o] = q; }
    }
    __syncthreads();
    if (threadIdx.x < 64) {
        int o = threadIdx.x & 31, which = threadIdx.x >> 5;
        float s = 0.f;
        #pragma unroll
        for (int ww = 0; ww < 8; ww++) s += which ? red_q[ww][o] : red_s[ww][o];
        atomicAdd(which ? &g_csum2[acc_off + oc0 + o] : &g_csum[acc_off + oc0 + o], (double)s);
    }
}

// ---------------- fused LSE + attentive pool, PPW points/warp, BN-finalize in prologue -----
// h stored in smem pre-packed as f32x2 (u64) pairs: phase-3 does zero packs. (R10-proven)
template<int C, int WARPS, int PPW>
__global__ void __launch_bounds__(WARPS*32) lse_pool_kernel(
    const float* __restrict__ Wl,  const float* __restrict__ bl,
    const float* __restrict__ lg,  const float* __restrict__ lbt,
    const float* __restrict__ Wp,  float* __restrict__ pooled) {
    constexpr int CPT = C / 32;
    constexpr int NT  = WARPS * 32;
    __shared__ float wl_sh[10 * C];
    __shared__ float wp_sh[C * C];
    __shared__ float prm_sh[3 * C];
    __shared__ float Cvs[10][10];
    __shared__ float mmf[10];
    __shared__ __align__(16) float s_sh[WARPS][16][12];
    __shared__ __align__(16) unsigned long long h_sh[WARPS][C][10];  // 8 used + pad

    const int tid = threadIdx.x;
    for (int t = tid; t < 10*C; t += NT) { int i = t / C, c = t % C; wl_sh[t] = Wl[c*10 + i]; }
    for (int t = tid; t < C*C;  t += NT) { int c = t / C, o = t % C; wp_sh[t] = Wp[o*(2*C) + c]; }
    const double P = (double)BB * NN * KK;
    if (tid < 10) mmf[tid] = (float)(g_msum[tid] / P);
    if (tid < 100) {
        int i = tid/10, j = tid%10;
        if (j >= i) {
            int off = 10 + i*10 - (i*(i-1))/2 + (j - i);
            float c = (float)(g_msum[off]/P - (g_msum[i]/P)*(g_msum[j]/P));
            Cvs[i][j] = c; Cvs[j][i] = c;
        }
    }
    __syncthreads();
    if (tid < C) {
        int o = tid;
        float wv[10];
        #pragma unroll
        for (int i = 0; i < 10; i++) wv[i] = wl_sh[i*C + o];
        float mean = bl[o];
        #pragma unroll
        for (int i = 0; i < 10; i++) mean = fmaf(wv[i], mmf[i], mean);
        float var = 0.f;
        #pragma unroll
        for (int i = 0; i < 10; i++) {
            float t = 0.f;
            #pragma unroll
            for (int j = 0; j < 10; j++) t = fmaf(wv[j], Cvs[i][j], t);
            var = fmaf(wv[i], t, var);
        }
        float scl = lg[o] / sqrtf(var + 1e-5f);
        prm_sh[o]       = bl[o];
        prm_sh[C + o]   = scl;
        prm_sh[2*C + o] = lbt[o] - mean*scl;
    }
    __syncthreads();

    const int w = tid >> 5, lane = tid & 31;

    float wlr[CPT][10], br[CPT], scr[CPT], shr[CPT];
    #pragma unroll
    for (int cc = 0; cc < CPT; cc++) {
        int c = lane + 32*cc;
        #pragma unroll
        for (int i = 0; i < 10; i++) wlr[cc][i] = wl_sh[i*C + c];
        br[cc] = prm_sh[c]; scr[cc] = prm_sh[C + c]; shr[cc] = prm_sh[2*C + c];
    }

    #pragma unroll 1
    for (int pp = 0; pp < PPW; pp++) {
        const int pt = (blockIdx.x * WARPS + w) * PPW + pp;
        const int b  = pt >> 13;
        const int n  = pt & (NN-1);

        if (lane < 16) {
            int gofs = (pt << 4) | lane;
            int j    = g_idx[gofs];
            float d  = g_dist[gofs];
            float4 ct = g_cpack[pt];
            float4 nb = g_cpack[(b << 13) + j];
            float* sr = s_sh[w][lane];
            sr[0]=ct.x; sr[1]=ct.y; sr[2]=ct.z;
            sr[3]=nb.x; sr[4]=nb.y; sr[5]=nb.z;
            sr[6]=ct.x-nb.x; sr[7]=ct.y-nb.y; sr[8]=ct.z-nb.z;
            sr[9]=d; sr[10]=0.f; sr[11]=0.f;
        }
        __syncwarp();

        // phase 2: h in registers, store pre-packed u64 pairs (4x STS.128)
        float hreg[CPT][16];
        #pragma unroll
        for (int k = 0; k < 16; k++) {
            const float4* sp = (const float4*)s_sh[w][k];
            float4 a0 = sp[0], a1 = sp[1], a2 = sp[2];
            float sv[10] = { a0.x,a0.y,a0.z,a0.w, a1.x,a1.y,a1.z,a1.w, a2.x,a2.y };
            #pragma unroll
            for (int cc = 0; cc < CPT; cc++) {
                float yv = br[cc];
                #pragma unroll
                for (int i = 0; i < 10; i++) yv = fmaf(wlr[cc][i], sv[i], yv);
                hreg[cc][k] = fmaxf(fmaf(yv, scr[cc], shr[cc]), 0.f);
            }
        }
        #pragma unroll
        for (int cc = 0; cc < CPT; cc++) {
            ulonglong2* dst = (ulonglong2*)&h_sh[w][lane + 32*cc][0];
            dst[0] = make_ulonglong2(pack2(hreg[cc][0],  hreg[cc][1]),
                                     pack2(hreg[cc][2],  hreg[cc][3]));
            dst[1] = make_ulonglong2(pack2(hreg[cc][4],  hreg[cc][5]),
                                     pack2(hreg[cc][6],  hreg[cc][7]));
            dst[2] = make_ulonglong2(pack2(hreg[cc][8],  hreg[cc][9]),
                                     pack2(hreg[cc][10], hreg[cc][11]));
            dst[3] = make_ulonglong2(pack2(hreg[cc][12], hreg[cc][13]),
                                     pack2(hreg[cc][14], hreg[cc][15]));
        }
        __syncwarp();

        // phase 3: score GEMM, packed operands straight from smem
        unsigned long long acc2[CPT][8];
        #pragma unroll
        for (int cc = 0; cc < CPT; cc++)
            #pragma unroll
            for (int k2 = 0; k2 < 8; k2++) acc2[cc][k2] = 0ULL;

        #pragma unroll 4
        for (int c = 0; c < C; c++) {
            const ulonglong2* hp = (const ulonglong2*)&h_sh[w][c][0];
            ulonglong2 A = hp[0], Bq = hp[1], Cq = hp[2], D = hp[3];
            unsigned long long hv2[8] = { A.x, A.y, Bq.x, Bq.y, Cq.x, Cq.y, D.x, D.y };
            #pragma unroll
            for (int cc = 0; cc < CPT; cc++) {
                float wv = wp_sh[c*C + lane + 32*cc];
                unsigned long long w2 = pack2(wv, wv);
                #pragma unroll
                for (int k2 = 0; k2 < 8; k2++) acc2[cc][k2] = ffma2(w2, hv2[k2], acc2[cc][k2]);
            }
        }

        // phase 4: softmax over K + weighted sum (h from registers)
        #pragma unroll
        for (int cc = 0; cc < CPT; cc++) {
            int o = lane + 32*cc;
            float acc[16];
            #pragma unroll
            for (int k2 = 0; k2 < 8; k2++) {
                float2 u = unpack2(acc2[cc][k2]);
                acc[2*k2] = u.x; acc[2*k2+1] = u.y;
            }
            float m = acc[0];
            #pragma unroll
            for (int k = 1; k < 16; k++) m = fmaxf(m, acc[k]);
            float se = 0.f;
            #pragma unroll
            for (int k = 0; k < 16; k++) { acc[k] = __expf(acc[k] - m); se += acc[k]; }
            float sum = 0.f;
            #pragma unroll
            for (int k = 0; k < 16; k++) sum = fmaf(acc[k], hreg[cc][k], sum);
            pooled[((b*C + o) << 13) + n] = sum / se;
        }
        __syncwarp();
    }
}

// ---------------- final: BN params in-block, BN+ReLU+concat, grid-stride float4 ----
__global__ void __launch_bounds__(256) final_kernel(
    const float* __restrict__ gm, const float* __restrict__ btm,
    const float* __restrict__ gr, const float* __restrict__ btr,
    float4* __restrict__ out) {
    __shared__ float scm[128], shm[128], scr_[128], shr_[128];
    const double P = (double)(BB*NN);
    {
        int t = threadIdx.x;
        int off = (t < 128) ? 96 : 224;
        int o   = t & 127;
        double mean = g_csum[off + o] / P;
        double var  = g_csum2[off + o] / P - mean*mean;
        const float* gg = (t < 128) ? gm : gr;
        const float* bb = (t < 128) ? btm : btr;
        double scl = (double)gg[o] / sqrt(var + 1e-5);
        if (t < 128) { scm[o] = (float)scl; shm[o] = (float)((double)bb[o] - mean*scl); }
        else         { scr_[o] = (float)scl; shr_[o] = (float)((double)bb[o] - mean*scl); }
    }
    __syncthreads();
    const int total = BB*256*NN/4;
    for (int t = (blockIdx.x << 8) + threadIdx.x; t < total; t += 1024*256) {
        int base = t << 2;
        int b  = base >> 21;
        int r  = base & ((1 << 21) - 1);
        int ch = r >> 13;
        int n  = r & (NN-1);
        float4 v; float sc, sh;
        if (ch < 128) {
            v = *(const float4*)&g_ymain[((b*128 + ch) << 13) + n];
            sc = scm[ch]; sh = shm[ch];
        } else {
            int c = ch - 128;
            v = *(const float4*)&g_yres[((b*128 + c) << 13) + n];
            sc = scr_[c]; sh = shr_[c];
        }
        v.x = fmaxf(fmaf(v.x, sc, sh), 0.f);
        v.y = fmaxf(fmaf(v.y, sc, sh), 0.f);
        v.z = fmaxf(fmaf(v.z, sc, sh), 0.f);
        v.w = fmaxf(fmaf(v.w, sc, sh), 0.f);
        out[t] = v;
    }
}

// ---------------- launch ----------------
extern "C" void kernel_launch(void* const* d_in, const int* in_sizes, int n_in,
                              void* d_out, int out_size) {
    const float* coords   = (const float*)d_in[0];
    const float* features = (const float*)d_in[1];
    const float* mlp1_w  = (const float*)d_in[2];
    const float* mlp1_b  = (const float*)d_in[3];
    const float* mlp1_g  = (const float*)d_in[4];
    const float* mlp1_bt = (const float*)d_in[5];
    const float* lse1_w  = (const float*)d_in[6];
    const float* lse1_b  = (const float*)d_in[7];
    const float* lse1_g  = (const float*)d_in[8];
    const float* lse1_bt = (const float*)d_in[9];
    const float* mlpp1_w  = (const float*)d_in[10];
    const float* mlpp1_b  = (const float*)d_in[11];
    const float* mlpp1_g  = (const float*)d_in[12];
    const float* mlpp1_bt = (const float*)d_in[13];
    const float* lse2_w  = (const float*)d_in[14];
    const float* lse2_b  = (const float*)d_in[15];
    const float* lse2_g  = (const float*)d_in[16];
    const float* lse2_bt = (const float*)d_in[17];
    const float* mlp2_w  = (const float*)d_in[18];
    const float* mlp2_b  = (const float*)d_in[19];
    const float* mlp2_g  = (const float*)d_in[20];
    const float* mlp2_bt = (const float*)d_in[21];
    const float* res_w  = (const float*)d_in[22];
    const float* res_b  = (const float*)d_in[23];
    const float* res_g  = (const float*)d_in[24];
    const float* res_bt = (const float*)d_in[25];
    const float* pool1_w = (const float*)d_in[26];
    const float* pool2_w = (const float*)d_in[28];
    float* out = (float*)d_out;

    void *p_y1, *p_pool1, *p_y2, *p_pool2, *p_ymain, *p_yres;
    cudaGetSymbolAddress(&p_y1, g_y1);       cudaGetSymbolAddress(&p_pool1, g_pool1);
    cudaGetSymbolAddress(&p_y2, g_y2);       cudaGetSymbolAddress(&p_pool2, g_pool2);
    cudaGetSymbolAddress(&p_ymain, g_ymain); cudaGetSymbolAddress(&p_yres, g_yres);

    static bool attr_done = false;
    if (!attr_done) {
        cudaFuncSetAttribute(knn_kernel, cudaFuncAttributeMaxDynamicSharedMemorySize, 90112);
        attr_done = true;
    }

    // 1) pack (zeros accumulators)
    pack_kernel<<<64, 256>>>(coords);
    // 2) fused conv: mlp1 + res from features
    convA_kernel<<<dim3(64,6), 256>>>(features, mlp1_w, mlp1_b, res_w, res_b,
                                      (float*)p_y1, (float*)p_yres);
    // 3) knn
    knn_kernel<<<256, 512, 90112>>>();
    // 4) spatial moments (4 samples/thread, 128thr x 512 blocks)
    moments_kernel<<<512, 128>>>();
    // 5) lse1 + pool1 (PPW=8)
    lse_pool_kernel<64,4,8><<<512, 128>>>(lse1_w, lse1_b, lse1_g, lse1_bt,
                                          pool1_w, (float*)p_pool1);
    // 6) mlpp1
    convB_kernel<128,64><<<dim3(64,1), 256>>>((float*)p_pool1, (float*)p_y1, mlpp1_w, mlpp1_b,
                                              mlp1_g, mlp1_bt, 0, 0.2f, (float*)p_y2, 32, 64);
    // 7) lse2 + pool2 (PPW=8)
    lse_pool_kernel<32,8,8><<<256, 256>>>(lse2_w, lse2_b, lse2_g, lse2_bt,
                                          pool2_w, (float*)p_pool2);
    // 8) mlp2
    convB_kernel<64,32><<<dim3(64,4), 256>>>((float*)p_pool2, (float*)p_y2, mlp2_w, mlp2_b,
                                             mlpp1_g, mlpp1_bt, 64, 0.0f, (float*)p_ymain, 128, 96);
    // 9) final
    final_kernel<<<1024, 256>>>(mlp2_g, mlp2_bt, res_g, res_bt, (float4*)out);
}

// round 15
// speedup vs baseline: 1.1417x; 1.0004x over previous
#include <cuda_runtime.h>
#include <math.h>
#include <stdint.h>

#define BB 2
#define NN 8192
#define KK 16

// ---------------- f32x2 packed-math helpers (sm_100+ PTX) ----------------
__device__ __forceinline__ unsigned long long ffma2(unsigned long long a, unsigned long long b,
                                                    unsigned long long c) {
    unsigned long long d;
    asm("fma.rn.f32x2 %0, %1, %2, %3;" : "=l"(d) : "l"(a), "l"(b), "l"(c));
    return d;
}
__device__ __forceinline__ unsigned long long pack2(float x, float y) {
    unsigned long long d;
    asm("mov.b64 %0, {%1, %2};" : "=l"(d) : "f"(x), "f"(y));
    return d;
}
__device__ __forceinline__ float2 unpack2(unsigned long long v) {
    float2 r;
    asm("mov.b64 {%0, %1}, %2;" : "=f"(r.x), "=f"(r.y) : "l"(v));
    return r;
}

// ---------------- scratch (static device globals; no allocation) ----------------
__device__ __align__(16) float4 g_cpack[BB*NN];   // raw coords + |c|^2
__device__ __align__(16) float4 g_cneg [BB*NN];   // (-2x,-2y,-2z, |c|^2) for KNN
__device__ __align__(16) int    g_idx [BB*NN*KK];
__device__ __align__(16) float  g_dist[BB*NN*KK];
__device__ __align__(16) float  g_y1   [BB*64 *NN];
__device__ __align__(16) float  g_pool1[BB*64 *NN];
__device__ __align__(16) float  g_y2   [BB*32 *NN];
__device__ __align__(16) float  g_pool2[BB*32 *NN];
__device__ __align__(16) float  g_ymain[BB*128*NN];
__device__ __align__(16) float  g_yres [BB*128*NN];
__device__ double g_msum[65];
__device__ double g_csum [352];   // [0,64)=mlp1 [64,96)=mlpp1 [96,224)=mlp2 [224,352)=res
__device__ double g_csum2[352];

// ---------------- pack coords + squared norm; zero accumulators ----------------
__global__ void __launch_bounds__(256) pack_kernel(const float* __restrict__ coords) {
    int p = (blockIdx.x << 8) + threadIdx.x;          // < BB*NN
    float x = coords[p*3+0], y = coords[p*3+1], z = coords[p*3+2];
    float w = fmaf(x, x, fmaf(y, y, z*z));
    g_cpack[p] = make_float4(x, y, z, w);
    g_cneg[p]  = make_float4(-2.f*x, -2.f*y, -2.f*z, w);
    if (p < 352) { g_csum[p] = 0.0; g_csum2[p] = 0.0; }
    if (p < 65)  g_msum[p] = 0.0;
}

// ---------------- KNN v6 (R10-proven): 4 queries/warp, queue + pivot-shrink ----------------
__device__ __forceinline__ float knn_exact16(float* qd, int* qi, float* td, int* ti,
                                             int lane, int& cnt) {
    const float INF = __int_as_float(0x7f800000);
    for (int s = cnt + lane; s < 128; s += 32) qd[s] = INF;
    __syncwarp();
    #pragma unroll 1
    for (int r = 0; r < 16; r++) {
        unsigned u  = __float_as_uint(qd[lane]);      int p = lane;
        unsigned u1 = __float_as_uint(qd[lane + 32]);
        unsigned u2 = __float_as_uint(qd[lane + 64]);
        unsigned u3 = __float_as_uint(qd[lane + 96]);
        if (u1 < u) { u = u1; p = lane + 32; }
        if (u2 < u) { u = u2; p = lane + 64; }
        if (u3 < u) { u = u3; p = lane + 96; }
        unsigned m  = __reduce_min_sync(0xffffffffu, u);
        unsigned z  = (u == m) ? (unsigned)p : 0xFFFFu;
        unsigned pm = __reduce_min_sync(0xffffffffu, z);
        if (lane == 0) {
            td[r] = __uint_as_float(m);
            ti[r] = qi[pm];
            qd[pm] = INF;
        }
        __syncwarp();
    }
    cnt = 0;
    __syncwarp();
    return td[15];
}

__device__ __forceinline__ float knn_shrink(float* qd, int* qi, float* td, int* ti,
                                            int lane, const unsigned lt, int& cnt) {
    const float INF = __int_as_float(0x7f800000);
    for (int s = cnt + lane; s < 128; s += 32) qd[s] = INF;
    __syncwarp();
    float v0 = qd[lane], v1 = qd[lane + 32], v2 = qd[lane + 64], v3 = qd[lane + 96];
    float mn = fminf(fminf(v0, v1), fminf(v2, v3));
    float mx = fmaxf(fmaxf(v0 < INF ? v0 : -INF, v1 < INF ? v1 : -INF),
                     fmaxf(v2 < INF ? v2 : -INF, v3 < INF ? v3 : -INF));
    #pragma unroll
    for (int off = 16; off; off >>= 1) {
        mn = fminf(mn, __shfl_xor_sync(0xffffffffu, mn, off));
        mx = fmaxf(mx, __shfl_xor_sync(0xffffffffu, mx, off));
    }
    float lo = mn, hi = mx;
    int hc = cnt;
    #pragma unroll 1
    for (int it = 0; it < 14 && hc > 64; it++) {
        float mid = 0.5f * (lo + hi);
        if (!(mid > lo) || !(mid < hi)) break;
        int c = (int)(v0 <= mid) + (int)(v1 <= mid) + (int)(v2 <= mid) + (int)(v3 <= mid);
        c = (int)__reduce_add_sync(0xffffffffu, (unsigned)c);
        if (c >= 16) { hi = mid; hc = c; } else lo = mid;
    }
    if (hc > 96) {                          // pathological duplicates: exact reset
        float tau = knn_exact16(qd, qi, td, ti, lane, cnt);
        if (lane < 16) { qd[lane] = td[lane]; qi[lane] = ti[lane]; }
        cnt = 16;
        __syncwarp();
        return tau;
    }
    int nc = 0;
    #pragma unroll
    for (int g = 0; g < 4; g++) {
        float v = (g == 0) ? v0 : (g == 1) ? v1 : (g == 2) ? v2 : v3;
        int idx = qi[lane + (g << 5)];
        bool keep = v <= hi;
        unsigned m = __ballot_sync(0xffffffffu, keep);
        if (keep) {
            int pos = nc + __popc(m & lt);
            qd[pos] = v;
            qi[pos] = idx;
        }
        nc += __popc(m);
    }
    cnt = nc;
    __syncwarp();
    return hi;
}

__global__ void __launch_bounds__(512, 2) knn_kernel() {
    extern __shared__ char dyn[];
    float4* tile = (float4*)dyn;                       // 1024*16 = 16384
    float*  qds  = (float*)(dyn + 16384);              // 64*128*4 = 32768
    int*    qis  = (int*)  (dyn + 49152);              // 32768
    float*  tds  = (float*)(dyn + 81920);              // 4096
    int*    tis  = (int*)  (dyn + 86016);              // 4096  (total 90112)

    const float INF = __int_as_float(0x7f800000);
    const int tid = threadIdx.x, w = tid >> 5, lane = tid & 31;
    const int b     = blockIdx.x >> 7;
    const int qbase = ((blockIdx.x & 127) << 6) | (w << 2);
    const int qslot = w << 2;
    const unsigned lt = (1u << lane) - 1u;

    float* qd0 = qds + ((qslot+0) << 7); int* qi0 = qis + ((qslot+0) << 7);
    float* qd1 = qds + ((qslot+1) << 7); int* qi1 = qis + ((qslot+1) << 7);
    float* qd2 = qds + ((qslot+2) << 7); int* qi2 = qis + ((qslot+2) << 7);
    float* qd3 = qds + ((qslot+3) << 7); int* qi3 = qis + ((qslot+3) << 7);
    float* td0 = tds + ((qslot+0) << 4); int* ti0 = tis + ((qslot+0) << 4);
    float* td1 = tds + ((qslot+1) << 4); int* ti1 = tis + ((qslot+1) << 4);
    float* td2 = tds + ((qslot+2) << 4); int* ti2 = tis + ((qslot+2) << 4);
    float* td3 = tds + ((qslot+3) << 4); int* ti3 = tis + ((qslot+3) << 4);

    const float4 q0 = g_cpack[(b << 13) + qbase + 0];
    const float4 q1 = g_cpack[(b << 13) + qbase + 1];
    const float4 q2 = g_cpack[(b << 13) + qbase + 2];
    const float4 q3 = g_cpack[(b << 13) + qbase + 3];
    const int n0 = qbase, n1 = qbase+1, n2 = qbase+2, n3 = qbase+3;
    float t0 = INF, t1 = INF, t2 = INF, t3 = INF;
    int c0 = 0, c1 = 0, c2 = 0, c3 = 0;

    for (int t = 0; t < 8; t++) {
        __syncthreads();
        tile[tid]       = g_cneg[(b << 13) + (t << 10) + tid];
        tile[tid + 512] = g_cneg[(b << 13) + (t << 10) + tid + 512];
        __syncthreads();
        const int jb = t << 10;
        #pragma unroll 1
        for (int s = 0; s < 32; s++) {
            float4 cc = tile[(s << 5) + lane];
            int j = jb + (s << 5) + lane;
            float e0 = fmaf(cc.x, q0.x, fmaf(cc.y, q0.y, fmaf(cc.z, q0.z, cc.w)));
            float e1 = fmaf(cc.x, q1.x, fmaf(cc.y, q1.y, fmaf(cc.z, q1.z, cc.w)));
            float e2 = fmaf(cc.x, q2.x, fmaf(cc.y, q2.y, fmaf(cc.z, q2.z, cc.w)));
            float e3 = fmaf(cc.x, q3.x, fmaf(cc.y, q3.y, fmaf(cc.z, q3.z, cc.w)));
            bool p0 = e0 < t0, p1 = e1 < t1, p2 = e2 < t2, p3 = e3 < t3;
            if (__ballot_sync(0xffffffffu, p0 | p1 | p2 | p3)) {
                unsigned m;
                #define KNN_PROC(P, E, QW, NQ, QD, QI, TD, TI, CN, TH)                      \
                    m = __ballot_sync(0xffffffffu, P);                                      \
                    if (m) {                                                                \
                        if (P) {                                                            \
                            int pos = CN + __popc(m & lt);                                  \
                            QD[pos] = (j == NQ) ? INF : fmaxf(E + QW, 0.f);                 \
                            QI[pos] = j;                                                    \
                        }                                                                   \
                        CN += __popc(m);                                                    \
                        if (CN > 96) TH = knn_shrink(QD, QI, TD, TI, lane, lt, CN) - QW;    \
                    }
                KNN_PROC(p0, e0, q0.w, n0, qd0, qi0, td0, ti0, c0, t0)
                KNN_PROC(p1, e1, q1.w, n1, qd1, qi1, td1, ti1, c1, t1)
                KNN_PROC(p2, e2, q2.w, n2, qd2, qi2, td2, ti2, c2, t2)
                KNN_PROC(p3, e3, q3.w, n3, qd3, qi3, td3, ti3, c3, t3)
                #undef KNN_PROC
            }
        }
    }
    knn_exact16(qd0, qi0, td0, ti0, lane, c0);
    knn_exact16(qd1, qi1, td1, ti1, lane, c1);
    knn_exact16(qd2, qi2, td2, ti2, lane, c2);
    knn_exact16(qd3, qi3, td3, ti3, lane, c3);

    if (lane < 16) {
        int base = ((b << 13) + qbase) << 4;
        g_idx [base + lane]      = ti0[lane];
        g_dist[base + lane]      = td0[lane];
        g_idx [base + 16 + lane] = ti1[lane];
        g_dist[base + 16 + lane] = td1[lane];
        g_idx [base + 32 + lane] = ti2[lane];
        g_dist[base + 32 + lane] = td2[lane];
        g_idx [base + 48 + lane] = ti3[lane];
        g_dist[base + 48 + lane] = td3[lane];
    }
}

// ---------------- spatial moments: 4 samples/thread, batched vector loads -----------------
__global__ void __launch_bounds__(128) moments_kernel() {
    const int tid = threadIdx.x;
    const int p0  = (((blockIdx.x << 7) + tid) << 2);  // grid 512: covers BB*NN*KK
    const int bn  = p0 >> 4;                           // same for all 4 samples
    const int b   = bn >> 13;
    // batched loads: idx4 + dist4 + ct in flight together, then 4 independent gathers
    int4   jj = *(const int4*)&g_idx[p0];
    float4 dd = *(const float4*)&g_dist[p0];
    float4 ct = g_cpack[bn];
    float4 nb0 = g_cpack[(b << 13) + jj.x];
    float4 nb1 = g_cpack[(b << 13) + jj.y];
    float4 nb2 = g_cpack[(b << 13) + jj.z];
    float4 nb3 = g_cpack[(b << 13) + jj.w];

    float a[65];
    #pragma unroll
    for (int v = 0; v < 65; v++) a[v] = 0.f;
    #pragma unroll
    for (int q = 0; q < 4; q++) {
        float4 nb = (q == 0) ? nb0 : (q == 1) ? nb1 : (q == 2) ? nb2 : nb3;
        float d   = (q == 0) ? dd.x : (q == 1) ? dd.y : (q == 2) ? dd.z : dd.w;
        float s[10] = { ct.x, ct.y, ct.z, nb.x, nb.y, nb.z,
                        ct.x-nb.x, ct.y-nb.y, ct.z-nb.z, d };
        int c2 = 10;
        #pragma unroll
        for (int i = 0; i < 10; i++) {
            a[i] += s[i];
            #pragma unroll
            for (int j2 = i; j2 < 10; j2++) { a[c2] = fmaf(s[i], s[j2], a[c2]); c2++; }
        }
    }
    __shared__ double sacc[65];
    if (tid < 65) sacc[tid] = 0.0;
    __syncthreads();
    #pragma unroll
    for (int v = 0; v < 65; v++) {
        float x = a[v];
        #pragma unroll
        for (int off = 16; off; off >>= 1) x += __shfl_down_sync(0xffffffffu, x, off);
        if ((tid & 31) == 0) atomicAdd(&sacc[v], (double)x);
    }
    __syncthreads();
    if (tid < 65) atomicAdd(&g_msum[tid], sacc[tid]);
}

// ---------------- fused conv A: features -> mlp1(64ch) + res(128ch), BN stats fused --------
__global__ void __launch_bounds__(256) convA_kernel(
    const float* __restrict__ feat,
    const float* __restrict__ w1, const float* __restrict__ b1,
    const float* __restrict__ w2, const float* __restrict__ b2,
    float* __restrict__ y1, float* __restrict__ yres) {
    __shared__ __align__(16) float Wsh[32*32];
    __shared__ float bsh[32];
    __shared__ float red_s[8][32], red_q[8][32];
    const int by = blockIdx.y;   // 0..5 : 0-1 -> mlp1, 2-5 -> res
    const float* W;  const float* bias;  float* y;  int oc0, CO, acc_off;
    if (by < 2) { W = w1; bias = b1; y = y1;   oc0 = by << 5;       CO = 64;  acc_off = 0; }
    else        { W = w2; bias = b2; y = yres; oc0 = (by - 2) << 5; CO = 128; acc_off = 224; }
    for (int t = threadIdx.x; t < 32*32; t += 256) {
        int i = t >> 5, ol = t & 31;
        Wsh[t] = W[(oc0 + ol)*32 + i];
    }
    if (threadIdx.x < 32) bsh[threadIdx.x] = bias[oc0 + threadIdx.x];
    __syncthreads();
    const int p = (blockIdx.x << 8) + threadIdx.x;
    const int b = p >> 13, n = p & (NN-1);
    const int w = threadIdx.x >> 5, lane = threadIdx.x & 31;
    unsigned long long acc2[16];
    #pragma unroll
    for (int o2 = 0; o2 < 16; o2++) acc2[o2] = pack2(bsh[2*o2], bsh[2*o2+1]);
    #pragma unroll 2
    for (int i = 0; i < 32; i++) {
        float x = feat[((b*32 + i) << 13) + n];
        unsigned long long x2 = pack2(x, x);
        const unsigned long long* wr = (const unsigned long long*)&Wsh[i << 5];
        #pragma unroll
        for (int o2 = 0; o2 < 16; o2++) acc2[o2] = ffma2(x2, wr[o2], acc2[o2]);
    }
    float acc[32];
    #pragma unroll
    for (int o2 = 0; o2 < 16; o2++) {
        float2 u = unpack2(acc2[o2]);
        acc[2*o2] = u.x; acc[2*o2+1] = u.y;
    }
    #pragma unroll
    for (int o = 0; o < 32; o++)
        y[((b*CO + oc0 + o) << 13) + n] = acc[o];
    #pragma unroll
    for (int o = 0; o < 32; o++) {
        float v = acc[o], q = v*v;
        #pragma unroll
        for (int off = 16; off; off >>= 1) {
            v += __shfl_xor_sync(0xffffffffu, v, off);
            q += __shfl_xor_sync(0xffffffffu, q, off);
        }
        if (lane == 0) { red_s[w][o] = v; red_q[w][o] = q; }
    }
    __syncthreads();
    if (threadIdx.x < 64) {
        int o = threadIdx.x & 31, which = threadIdx.x >> 5;
        float s = 0.f;
        #pragma unroll
        for (int ww = 0; ww < 8; ww++) s += which ? red_q[ww][o] : red_s[ww][o];
        atomicAdd(which ? &g_csum2[acc_off + oc0 + o] : &g_csum[acc_off + oc0 + o], (double)s);
    }
}

// ---------------- 1x1 conv (CI inputs), in1 gets in-place BN+act computed from g_csum -------
template<int CI, int CI0>
__global__ void __launch_bounds__(256) convB_kernel(
    const float* __restrict__ in0, const float* __restrict__ in1,
    const float* __restrict__ W,   const float* __restrict__ bias,
    const float* __restrict__ gprm, const float* __restrict__ btprm,
    int prm_off, float slope,
    float* __restrict__ y, int CO, int acc_off) {
    __shared__ __align__(16) float Wsh[CI*32];
    __shared__ float bsh[32];
    __shared__ float scsh[CI-CI0], shsh[CI-CI0];
    __shared__ float red_s[8][32], red_q[8][32];
    const int oc0 = blockIdx.y << 5;
    for (int t = threadIdx.x; t < CI*32; t += 256) {
        int i = t >> 5, ol = t & 31;
        Wsh[t] = W[(oc0 + ol)*CI + i];
    }
    if (threadIdx.x < 32) bsh[threadIdx.x] = bias[oc0 + threadIdx.x];
    if (threadIdx.x < (CI-CI0)) {
        int i = threadIdx.x;
        const double P = (double)(BB*NN);
        double mean = g_csum[prm_off + i] / P;
        double var  = g_csum2[prm_off + i] / P - mean*mean;
        double scl  = (double)gprm[i] / sqrt(var + 1e-5);
        scsh[i] = (float)scl;
        shsh[i] = (float)((double)btprm[i] - mean*scl);
    }
    __syncthreads();
    const int p = (blockIdx.x << 8) + threadIdx.x;
    const int b = p >> 13, n = p & (NN-1);
    const int w = threadIdx.x >> 5, lane = threadIdx.x & 31;
    unsigned long long acc2[16];
    #pragma unroll
    for (int o2 = 0; o2 < 16; o2++) acc2[o2] = pack2(bsh[2*o2], bsh[2*o2+1]);
    #pragma unroll 2
    for (int i = 0; i < CI0; i++) {
        float x = in0[((b*CI0 + i) << 13) + n];
        unsigned long long x2 = pack2(x, x);
        const unsigned long long* wr = (const unsigned long long*)&Wsh[i << 5];
        #pragma unroll
        for (int o2 = 0; o2 < 16; o2++) acc2[o2] = ffma2(x2, wr[o2], acc2[o2]);
    }
    #pragma unroll 2
    for (int i = 0; i < CI - CI0; i++) {
        float x = in1[((b*(CI-CI0) + i) << 13) + n];
        x = fmaf(x, scsh[i], shsh[i]);
        x = x > 0.f ? x : slope * x;
        unsigned long long x2 = pack2(x, x);
        const unsigned long long* wr = (const unsigned long long*)&Wsh[(CI0 + i) << 5];
        #pragma unroll
        for (int o2 = 0; o2 < 16; o2++) acc2[o2] = ffma2(x2, wr[o2], acc2[o2]);
    }
    float acc[32];
    #pragma unroll
    for (int o2 = 0; o2 < 16; o2++) {
        float2 u = unpack2(acc2[o2]);
        acc[2*o2] = u.x; acc[2*o2+1] = u.y;
    }
    #pragma unroll
    for (int o = 0; o < 32; o++)
        y[((b*CO + oc0 + o) << 13) + n] = acc[o];
    #pragma unroll
    for (int o = 0; o < 32; o++) {
        float v = acc[o], q = v*v;
        #pragma unroll
        for (int off = 16; off; off >>= 1) {
            v += __shfl_xor_sync(0xffffffffu, v, off);
            q += __shfl_xor_sync(0xffffffffu, q, off);
        }
        if (lane == 0) { red_s[w][o] = v; red_q[w][o] = q; }
    }
    __syncthreads();
    if (threadIdx.x < 64) {
        int o = threadIdx.x & 31, which = threadIdx.x >> 5;
        float s = 0.f;
        #pragma unroll
        for (int ww = 0; ww < 8; ww++) s += which ? red_q[ww][o] : red_s[ww][o];
        atomicAdd(which ? &g_csum2[acc_off + oc0 + o] : &g_csum[acc_off + oc0 + o], (double)s);
    }
}

// ---------------- fused LSE + attentive pool, PPW points/warp, BN-finalize in prologue -----
// h stored in smem pre-packed as f32x2 (u64) pairs: phase-3 does zero packs. (R10-proven)
template<int C, int WARPS, int PPW>
__global__ void __launch_bounds__(WARPS*32) lse_pool_kernel(
    const float* __restrict__ Wl,  const float* __restrict__ bl,
    const float* __restrict__ lg,  const float* __restrict__ lbt,
    const float* __restrict__ Wp,  float* __restrict__ pooled) {
    constexpr int CPT = C / 32;
    constexpr int NT  = WARPS * 32;
    __shared__ float wl_sh[10 * C];
    __shared__ float wp_sh[C * C];
    __shared__ float prm_sh[3 * C];
    __shared__ float Cvs[10][10];
    __shared__ float mmf[10];
    __shared__ __align__(16) float s_sh[WARPS][16][12];
    __shared__ __align__(16) unsigned long long h_sh[WARPS][C][10];  // 8 used + pad

    const int tid = threadIdx.x;
    for (int t = tid; t < 10*C; t += NT) { int i = t / C, c = t % C; wl_sh[t] = Wl[c*10 + i]; }
    for (int t = tid; t < C*C;  t += NT) { int c = t / C, o = t % C; wp_sh[t] = Wp[o*(2*C) + c]; }
    const double P = (double)BB * NN * KK;
    if (tid < 10) mmf[tid] = (float)(g_msum[tid] / P);
    if (tid < 100) {
        int i = tid/10, j = tid%10;
        if (j >= i) {
            int off = 10 + i*10 - (i*(i-1))/2 + (j - i);
            float c = (float)(g_msum[off]/P - (g_msum[i]/P)*(g_msum[j]/P));
            Cvs[i][j] = c; Cvs[j][i] = c;
        }
    }
    __syncthreads();
    if (tid < C) {
        int o = tid;
        float wv[10];
        #pragma unroll
        for (int i = 0; i < 10; i++) wv[i] = wl_sh[i*C + o];
        float mean = bl[o];
        #pragma unroll
        for (int i = 0; i < 10; i++) mean = fmaf(wv[i], mmf[i], mean);
        float var = 0.f;
        #pragma unroll
        for (int i = 0; i < 10; i++) {
            float t = 0.f;
            #pragma unroll
            for (int j = 0; j < 10; j++) t = fmaf(wv[j], Cvs[i][j], t);
            var = fmaf(wv[i], t, var);
        }
        float scl = lg[o] / sqrtf(var + 1e-5f);
        prm_sh[o]       = bl[o];
        prm_sh[C + o]   = scl;
        prm_sh[2*C + o] = lbt[o] - mean*scl;
    }
    __syncthreads();

    const int w = tid >> 5, lane = tid & 31;

    float wlr[CPT][10], br[CPT], scr[CPT], shr[CPT];
    #pragma unroll
    for (int cc = 0; cc < CPT; cc++) {
        int c = lane + 32*cc;
        #pragma unroll
        for (int i = 0; i < 10; i++) wlr[cc][i] = wl_sh[i*C + c];
        br[cc] = prm_sh[c]; scr[cc] = prm_sh[C + c]; shr[cc] = prm_sh[2*C + c];
    }

    #pragma unroll 1
    for (int pp = 0; pp < PPW; pp++) {
        const int pt = (blockIdx.x * WARPS + w) * PPW + pp;
        const int b  = pt >> 13;
        const int n  = pt & (NN-1);

        if (lane < 16) {
            int gofs = (pt << 4) | lane;
            int j    = g_idx[gofs];
            float d  = g_dist[gofs];
            float4 ct = g_cpack[pt];
            float4 nb = g_cpack[(b << 13) + j];
            float* sr = s_sh[w][lane];
            sr[0]=ct.x; sr[1]=ct.y; sr[2]=ct.z;
            sr[3]=nb.x; sr[4]=nb.y; sr[5]=nb.z;
            sr[6]=ct.x-nb.x; sr[7]=ct.y-nb.y; sr[8]=ct.z-nb.z;
            sr[9]=d; sr[10]=0.f; sr[11]=0.f;
        }
        __syncwarp();

        // phase 2: h in registers, store pre-packed u64 pairs (4x STS.128)
        float hreg[CPT][16];
        #pragma unroll
        for (int k = 0; k < 16; k++) {
            const float4* sp = (const float4*)s_sh[w][k];
            float4 a0 = sp[0], a1 = sp[1], a2 = sp[2];
            float sv[10] = { a0.x,a0.y,a0.z,a0.w, a1.x,a1.y,a1.z,a1.w, a2.x,a2.y };
            #pragma unroll
            for (int cc = 0; cc < CPT; cc++) {
                float yv = br[cc];
                #pragma unroll
                for (int i = 0; i < 10; i++) yv = fmaf(wlr[cc][i], sv[i], yv);
                hreg[cc][k] = fmaxf(fmaf(yv, scr[cc], shr[cc]), 0.f);
            }
        }
        #pragma unroll
        for (int cc = 0; cc < CPT; cc++) {
            ulonglong2* dst = (ulonglong2*)&h_sh[w][lane + 32*cc][0];
            dst[0] = make_ulonglong2(pack2(hreg[cc][0],  hreg[cc][1]),
                                     pack2(hreg[cc][2],  hreg[cc][3]));
            dst[1] = make_ulonglong2(pack2(hreg[cc][4],  hreg[cc][5]),
                                     pack2(hreg[cc][6],  hreg[cc][7]));
            dst[2] = make_ulonglong2(pack2(hreg[cc][8],  hreg[cc][9]),
                                     pack2(hreg[cc][10], hreg[cc][11]));
            dst[3] = make_ulonglong2(pack2(hreg[cc][12], hreg[cc][13]),
                                     pack2(hreg[cc][14], hreg[cc][15]));
        }
        __syncwarp();

        // phase 3: score GEMM, packed operands straight from smem
        unsigned long long acc2[CPT][8];
        #pragma unroll
        for (int cc = 0; cc < CPT; cc++)
            #pragma unroll
            for (int k2 = 0; k2 < 8; k2++) acc2[cc][k2] = 0ULL;

        #pragma unroll 4
        for (int c = 0; c < C; c++) {
            const ulonglong2* hp = (const ulonglong2*)&h_sh[w][c][0];
            ulonglong2 A = hp[0], Bq = hp[1], Cq = hp[2], D = hp[3];
            unsigned long long hv2[8] = { A.x, A.y, Bq.x, Bq.y, Cq.x, Cq.y, D.x, D.y };
            #pragma unroll
            for (int cc = 0; cc < CPT; cc++) {
                float wv = wp_sh[c*C + lane + 32*cc];
                unsigned long long w2 = pack2(wv, wv);
                #pragma unroll
                for (int k2 = 0; k2 < 8; k2++) acc2[cc][k2] = ffma2(w2, hv2[k2], acc2[cc][k2]);
            }
        }

        // phase 4: softmax over K + weighted sum (h from registers)
        #pragma unroll
        for (int cc = 0; cc < CPT; cc++) {
            int o = lane + 32*cc;
            float acc[16];
            #pragma unroll
            for (int k2 = 0; k2 < 8; k2++) {
                float2 u = unpack2(acc2[cc][k2]);
                acc[2*k2] = u.x; acc[2*k2+1] = u.y;
            }
            float m = acc[0];
            #pragma unroll
            for (int k = 1; k < 16; k++) m = fmaxf(m, acc[k]);
            float se = 0.f;
            #pragma unroll
            for (int k = 0; k < 16; k++) { acc[k] = __expf(acc[k] - m); se += acc[k]; }
            float sum = 0.f;
            #pragma unroll
            for (int k = 0; k < 16; k++) sum = fmaf(acc[k], hreg[cc][k], sum);
            pooled[((b*C + o) << 13) + n] = sum / se;
        }
        __syncwarp();
    }
}

// ---------------- final: BN params in-block, BN+ReLU+concat, grid-stride float4 ----
__global__ void __launch_bounds__(256) final_kernel(
    const float* __restrict__ gm, const float* __restrict__ btm,
    const float* __restrict__ gr, const float* __restrict__ btr,
    float4* __restrict__ out) {
    __shared__ float scm[128], shm[128], scr_[128], shr_[128];
    const double P = (double)(BB*NN);
    {
        int t = threadIdx.x;
        int off = (t < 128) ? 96 : 224;
        int o   = t & 127;
        double mean = g_csum[off + o] / P;
        double var  = g_csum2[off + o] / P - mean*mean;
        const float* gg = (t < 128) ? gm : gr;
        const float* bb = (t < 128) ? btm : btr;
        double scl = (double)gg[o] / sqrt(var + 1e-5);
        if (t < 128) { scm[o] = (float)scl; shm[o] = (float)((double)bb[o] - mean*scl); }
        else         { scr_[o] = (float)scl; shr_[o] = (float)((double)bb[o] - mean*scl); }
    }
    __syncthreads();
    const int total = BB*256*NN/4;
    for (int t = (blockIdx.x << 8) + threadIdx.x; t < total; t += 1024*256) {
        int base = t << 2;
        int b  = base >> 21;
        int r  = base & ((1 << 21) - 1);
        int ch = r >> 13;
        int n  = r & (NN-1);
        float4 v; float sc, sh;
        if (ch < 128) {
            v = *(const float4*)&g_ymain[((b*128 + ch) << 13) + n];
            sc = scm[ch]; sh = shm[ch];
        } else {
            int c = ch - 128;
            v = *(const float4*)&g_yres[((b*128 + c) << 13) + n];
            sc = scr_[c]; sh = shr_[c];
        }
        v.x = fmaxf(fmaf(v.x, sc, sh), 0.f);
        v.y = fmaxf(fmaf(v.y, sc, sh), 0.f);
        v.z = fmaxf(fmaf(v.z, sc, sh), 0.f);
        v.w = fmaxf(fmaf(v.w, sc, sh), 0.f);
        out[t] = v;
    }
}

// ---------------- launch ----------------
extern "C" void kernel_launch(void* const* d_in, const int* in_sizes, int n_in,
                              void* d_out, int out_size) {
    const float* coords   = (const float*)d_in[0];
    const float* features = (const float*)d_in[1];
    const float* mlp1_w  = (const float*)d_in[2];
    const float* mlp1_b  = (const float*)d_in[3];
    const float* mlp1_g  = (const float*)d_in[4];
    const float* mlp1_bt = (const float*)d_in[5];
    const float* lse1_w  = (const float*)d_in[6];
    const float* lse1_b  = (const float*)d_in[7];
    const float* lse1_g  = (const float*)d_in[8];
    const float* lse1_bt = (const float*)d_in[9];
    const float* mlpp1_w  = (const float*)d_in[10];
    const float* mlpp1_b  = (const float*)d_in[11];
    const float* mlpp1_g  = (const float*)d_in[12];
    const float* mlpp1_bt = (const float*)d_in[13];
    const float* lse2_w  = (const float*)d_in[14];
    const float* lse2_b  = (const float*)d_in[15];
    const float* lse2_g  = (const float*)d_in[16];
    const float* lse2_bt = (const float*)d_in[17];
    const float* mlp2_w  = (const float*)d_in[18];
    const float* mlp2_b  = (const float*)d_in[19];
    const float* mlp2_g  = (const float*)d_in[20];
    const float* mlp2_bt = (const float*)d_in[21];
    const float* res_w  = (const float*)d_in[22];
    const float* res_b  = (const float*)d_in[23];
    const float* res_g  = (const float*)d_in[24];
    const float* res_bt = (const float*)d_in[25];
    const float* pool1_w = (const float*)d_in[26];
    const float* pool2_w = (const float*)d_in[28];
    float* out = (float*)d_out;

    void *p_y1, *p_pool1, *p_y2, *p_pool2, *p_ymain, *p_yres;
    cudaGetSymbolAddress(&p_y1, g_y1);       cudaGetSymbolAddress(&p_pool1, g_pool1);
    cudaGetSymbolAddress(&p_y2, g_y2);       cudaGetSymbolAddress(&p_pool2, g_pool2);
    cudaGetSymbolAddress(&p_ymain, g_ymain); cudaGetSymbolAddress(&p_yres, g_yres);

    static cudaStream_t s2 = nullptr;
    static cudaEvent_t  e1 = nullptr, e2 = nullptr;
    static bool attr_done = false;
    if (!attr_done) {
        cudaFuncSetAttribute(knn_kernel, cudaFuncAttributeMaxDynamicSharedMemorySize, 90112);
        cudaStreamCreateWithFlags(&s2, cudaStreamNonBlocking);
        cudaEventCreateWithFlags(&e1, cudaEventDisableTiming);
        cudaEventCreateWithFlags(&e2, cudaEventDisableTiming);
        attr_done = true;
    }

    // 1) pack (zeros accumulators)
    pack_kernel<<<64, 256>>>(coords);
    // fork: convA (mlp1 + res from features) runs on side stream, overlapped with knn
    cudaEventRecord(e1, 0);
    cudaStreamWaitEvent(s2, e1, 0);
    convA_kernel<<<dim3(64,6), 256, 0, s2>>>(features, mlp1_w, mlp1_b, res_w, res_b,
                                             (float*)p_y1, (float*)p_yres);
    cudaEventRecord(e2, s2);
    // 2) knn (default stream, overlaps convA)
    knn_kernel<<<256, 512, 90112>>>();
    // 3) spatial moments (batched vector loads)
    moments_kernel<<<512, 128>>>();
    // 4) lse1 + pool1 (PPW=8)
    lse_pool_kernel<64,4,8><<<512, 128>>>(lse1_w, lse1_b, lse1_g, lse1_bt,
                                          pool1_w, (float*)p_pool1);
    // join: mlpp1 consumes y1 + csum from convA
    cudaStreamWaitEvent(0, e2, 0);
    // 5) mlpp1
    convB_kernel<128,64><<<dim3(64,1), 256>>>((float*)p_pool1, (float*)p_y1, mlpp1_w, mlpp1_b,
                                              mlp1_g, mlp1_bt, 0, 0.2f, (float*)p_y2, 32, 64);
    // 6) lse2 + pool2 (PPW=8)
    lse_pool_kernel<32,8,8><<<256, 256>>>(lse2_w, lse2_b, lse2_g, lse2_bt,
                                          pool2_w, (float*)p_pool2);
    // 7) mlp2
    convB_kernel<64,32><<<dim3(64,4), 256>>>((float*)p_pool2, (float*)p_y2, mlp2_w, mlp2_b,
                                             mlpp1_g, mlpp1_bt, 64, 0.0f, (float*)p_ymain, 128, 96);
    // 8) final
    final_kernel<<<1024, 256>>>(mlp2_g, mlp2_bt, res_g, res_bt, (float4*)out);
}

// round 16
// speedup vs baseline: 1.1736x; 1.0279x over previous
#include <cuda_runtime.h>
#include <math.h>
#include <stdint.h>

#define BB 2
#define NN 8192
#define KK 16

// ---------------- f32x2 packed-math helpers (sm_100+ PTX) ----------------
__device__ __forceinline__ unsigned long long ffma2(unsigned long long a, unsigned long long b,
                                                    unsigned long long c) {
    unsigned long long d;
    asm("fma.rn.f32x2 %0, %1, %2, %3;" : "=l"(d) : "l"(a), "l"(b), "l"(c));
    return d;
}
__device__ __forceinline__ unsigned long long pack2(float x, float y) {
    unsigned long long d;
    asm("mov.b64 %0, {%1, %2};" : "=l"(d) : "f"(x), "f"(y));
    return d;
}
__device__ __forceinline__ float2 unpack2(unsigned long long v) {
    float2 r;
    asm("mov.b64 {%0, %1}, %2;" : "=f"(r.x), "=f"(r.y) : "l"(v));
    return r;
}

// ---------------- scratch (static device globals; no allocation) ----------------
__device__ __align__(16) float4 g_cpack[BB*NN];   // raw coords + |c|^2
__device__ __align__(16) float4 g_cneg [BB*NN];   // (-2x,-2y,-2z, |c|^2) for KNN
__device__ __align__(16) int    g_idx [BB*NN*KK];
__device__ __align__(16) float  g_dist[BB*NN*KK];
__device__ __align__(16) float  g_y1   [BB*64 *NN];
__device__ __align__(16) float  g_pool1[BB*64 *NN];
__device__ __align__(16) float  g_y2   [BB*32 *NN];
__device__ __align__(16) float  g_pool2[BB*32 *NN];
__device__ __align__(16) float  g_ymain[BB*128*NN];
__device__ __align__(16) float  g_yres [BB*128*NN];
__device__ double g_msum[65];
__device__ double g_csum [352];   // [0,64)=mlp1 [64,96)=mlpp1 [96,224)=mlp2 [224,352)=res
__device__ double g_csum2[352];

// ---------------- pack coords + squared norm; zero accumulators ----------------
__global__ void __launch_bounds__(256) pack_kernel(const float* __restrict__ coords) {
    int p = (blockIdx.x << 8) + threadIdx.x;          // < BB*NN
    float x = coords[p*3+0], y = coords[p*3+1], z = coords[p*3+2];
    float w = fmaf(x, x, fmaf(y, y, z*z));
    g_cpack[p] = make_float4(x, y, z, w);
    g_cneg[p]  = make_float4(-2.f*x, -2.f*y, -2.f*z, w);
    if (p < 352) { g_csum[p] = 0.0; g_csum2[p] = 0.0; }
    if (p < 65)  g_msum[p] = 0.0;
}

// ---------------- KNN v7: 4 queries/warp, 96-slot queue + pivot-shrink --------------------
// queue always contains the true top-16-so-far; distances clamped >=0 (uint order == float).
__device__ __forceinline__ float knn_exact16(float* qd, int* qi, float* td, int* ti,
                                             int lane, int& cnt) {
    const float INF = __int_as_float(0x7f800000);
    for (int s = cnt + lane; s < 96; s += 32) qd[s] = INF;
    __syncwarp();
    #pragma unroll 1
    for (int r = 0; r < 16; r++) {
        unsigned u  = __float_as_uint(qd[lane]);      int p = lane;
        unsigned u1 = __float_as_uint(qd[lane + 32]);
        unsigned u2 = __float_as_uint(qd[lane + 64]);
        if (u1 < u) { u = u1; p = lane + 32; }
        if (u2 < u) { u = u2; p = lane + 64; }
        unsigned m  = __reduce_min_sync(0xffffffffu, u);
        unsigned z  = (u == m) ? (unsigned)p : 0xFFFFu;
        unsigned pm = __reduce_min_sync(0xffffffffu, z);
        if (lane == 0) {
            td[r] = __uint_as_float(m);
            ti[r] = qi[pm];
            qd[pm] = INF;
        }
        __syncwarp();
    }
    cnt = 0;
    __syncwarp();
    return td[15];
}

__device__ __forceinline__ float knn_shrink(float* qd, int* qi, float* td, int* ti,
                                            int lane, const unsigned lt, int& cnt) {
    const float INF = __int_as_float(0x7f800000);
    for (int s = cnt + lane; s < 96; s += 32) qd[s] = INF;
    __syncwarp();
    float v0 = qd[lane], v1 = qd[lane + 32], v2 = qd[lane + 64];
    float mn = fminf(fminf(v0, v1), v2);
    float mx = fmaxf(fmaxf(v0 < INF ? v0 : -INF, v1 < INF ? v1 : -INF),
                     (v2 < INF ? v2 : -INF));
    #pragma unroll
    for (int off = 16; off; off >>= 1) {
        mn = fminf(mn, __shfl_xor_sync(0xffffffffu, mn, off));
        mx = fmaxf(mx, __shfl_xor_sync(0xffffffffu, mx, off));
    }
    float lo = mn, hi = mx;
    int hc = cnt;
    #pragma unroll 1
    for (int it = 0; it < 14 && hc > 48; it++) {
        float mid = 0.5f * (lo + hi);
        if (!(mid > lo) || !(mid < hi)) break;
        int c = (int)(v0 <= mid) + (int)(v1 <= mid) + (int)(v2 <= mid);
        c = (int)__reduce_add_sync(0xffffffffu, (unsigned)c);
        if (c >= 16) { hi = mid; hc = c; } else lo = mid;
    }
    if (hc > 64) {                          // can't bisect below (duplicates): exact reset
        float tau = knn_exact16(qd, qi, td, ti, lane, cnt);
        if (lane < 16) { qd[lane] = td[lane]; qi[lane] = ti[lane]; }
        cnt = 16;
        __syncwarp();
        return tau;
    }
    int nc = 0;
    #pragma unroll
    for (int g = 0; g < 3; g++) {
        float v = (g == 0) ? v0 : (g == 1) ? v1 : v2;
        int idx = qi[lane + (g << 5)];
        bool keep = v <= hi;
        unsigned m = __ballot_sync(0xffffffffu, keep);
        if (keep) {
            int pos = nc + __popc(m & lt);
            qd[pos] = v;
            qi[pos] = idx;
        }
        nc += __popc(m);
    }
    cnt = nc;
    __syncwarp();
    return hi;
}

__global__ void __launch_bounds__(512, 2) knn_kernel() {
    extern __shared__ char dyn[];
    float4* tile = (float4*)dyn;                       // 1024*16 = 16384
    float*  qds  = (float*)(dyn + 16384);              // 64*96*4 = 24576
    int*    qis  = (int*)  (dyn + 40960);              // 24576
    float*  tds  = (float*)(dyn + 65536);              // 4096
    int*    tis  = (int*)  (dyn + 69632);              // 4096  (total 73728)

    const float INF = __int_as_float(0x7f800000);
    const int tid = threadIdx.x, w = tid >> 5, lane = tid & 31;
    const int b     = blockIdx.x >> 7;
    const int qbase = ((blockIdx.x & 127) << 6) | (w << 2);
    const int qslot = w << 2;
    const unsigned lt = (1u << lane) - 1u;

    float* qd0 = qds + (qslot+0)*96; int* qi0 = qis + (qslot+0)*96;
    float* qd1 = qds + (qslot+1)*96; int* qi1 = qis + (qslot+1)*96;
    float* qd2 = qds + (qslot+2)*96; int* qi2 = qis + (qslot+2)*96;
    float* qd3 = qds + (qslot+3)*96; int* qi3 = qis + (qslot+3)*96;
    float* td0 = tds + ((qslot+0) << 4); int* ti0 = tis + ((qslot+0) << 4);
    float* td1 = tds + ((qslot+1) << 4); int* ti1 = tis + ((qslot+1) << 4);
    float* td2 = tds + ((qslot+2) << 4); int* ti2 = tis + ((qslot+2) << 4);
    float* td3 = tds + ((qslot+3) << 4); int* ti3 = tis + ((qslot+3) << 4);

    const float4 q0 = g_cpack[(b << 13) + qbase + 0];
    const float4 q1 = g_cpack[(b << 13) + qbase + 1];
    const float4 q2 = g_cpack[(b << 13) + qbase + 2];
    const float4 q3 = g_cpack[(b << 13) + qbase + 3];
    const int n0 = qbase, n1 = qbase+1, n2 = qbase+2, n3 = qbase+3;
    float t0 = INF, t1 = INF, t2 = INF, t3 = INF;
    int c0 = 0, c1 = 0, c2 = 0, c3 = 0;

    for (int t = 0; t < 8; t++) {
        __syncthreads();
        tile[tid]       = g_cneg[(b << 13) + (t << 10) + tid];
        tile[tid + 512] = g_cneg[(b << 13) + (t << 10) + tid + 512];
        __syncthreads();
        const int jb = t << 10;
        #pragma unroll 1
        for (int s = 0; s < 32; s++) {
            float4 cc = tile[(s << 5) + lane];
            int j = jb + (s << 5) + lane;
            float e0 = fmaf(cc.x, q0.x, fmaf(cc.y, q0.y, fmaf(cc.z, q0.z, cc.w)));
            float e1 = fmaf(cc.x, q1.x, fmaf(cc.y, q1.y, fmaf(cc.z, q1.z, cc.w)));
            float e2 = fmaf(cc.x, q2.x, fmaf(cc.y, q2.y, fmaf(cc.z, q2.z, cc.w)));
            float e3 = fmaf(cc.x, q3.x, fmaf(cc.y, q3.y, fmaf(cc.z, q3.z, cc.w)));
            bool p0 = e0 < t0, p1 = e1 < t1, p2 = e2 < t2, p3 = e3 < t3;
            if (__ballot_sync(0xffffffffu, p0 | p1 | p2 | p3)) {
                unsigned m;
                #define KNN_PROC(P, E, QW, NQ, QD, QI, TD, TI, CN, TH)                      \
                    m = __ballot_sync(0xffffffffu, P);                                      \
                    if (m) {                                                                \
                        if (P) {                                                            \
                            int pos = CN + __popc(m & lt);                                  \
                            QD[pos] = (j == NQ) ? INF : fmaxf(E + QW, 0.f);                 \
                            QI[pos] = j;                                                    \
                        }                                                                   \
                        CN += __popc(m);                                                    \
                        if (CN > 64) TH = knn_shrink(QD, QI, TD, TI, lane, lt, CN) - QW;    \
                    }
                KNN_PROC(p0, e0, q0.w, n0, qd0, qi0, td0, ti0, c0, t0)
                KNN_PROC(p1, e1, q1.w, n1, qd1, qi1, td1, ti1, c1, t1)
                KNN_PROC(p2, e2, q2.w, n2, qd2, qi2, td2, ti2, c2, t2)
                KNN_PROC(p3, e3, q3.w, n3, qd3, qi3, td3, ti3, c3, t3)
                #undef KNN_PROC
            }
        }
    }
    knn_exact16(qd0, qi0, td0, ti0, lane, c0);
    knn_exact16(qd1, qi1, td1, ti1, lane, c1);
    knn_exact16(qd2, qi2, td2, ti2, lane, c2);
    knn_exact16(qd3, qi3, td3, ti3, lane, c3);

    if (lane < 16) {
        int base = ((b << 13) + qbase) << 4;
        g_idx [base + lane]      = ti0[lane];
        g_dist[base + lane]      = td0[lane];
        g_idx [base + 16 + lane] = ti1[lane];
        g_dist[base + 16 + lane] = td1[lane];
        g_idx [base + 32 + lane] = ti2[lane];
        g_dist[base + 32 + lane] = td2[lane];
        g_idx [base + 48 + lane] = ti3[lane];
        g_dist[base + 48 + lane] = td3[lane];
    }
}

// ---------------- spatial moments: 4 samples/thread, batched vector loads, 256x256 --------
__global__ void __launch_bounds__(256) moments_kernel() {
    const int tid = threadIdx.x;
    const int p0  = (((blockIdx.x << 8) + tid) << 2);  // grid 256: covers BB*NN*KK
    const int bn  = p0 >> 4;                           // same for all 4 samples
    const int b   = bn >> 13;
    int4   jj = *(const int4*)&g_idx[p0];
    float4 dd = *(const float4*)&g_dist[p0];
    float4 ct = g_cpack[bn];
    float4 nb0 = g_cpack[(b << 13) + jj.x];
    float4 nb1 = g_cpack[(b << 13) + jj.y];
    float4 nb2 = g_cpack[(b << 13) + jj.z];
    float4 nb3 = g_cpack[(b << 13) + jj.w];

    float a[65];
    #pragma unroll
    for (int v = 0; v < 65; v++) a[v] = 0.f;
    #pragma unroll
    for (int q = 0; q < 4; q++) {
        float4 nb = (q == 0) ? nb0 : (q == 1) ? nb1 : (q == 2) ? nb2 : nb3;
        float d   = (q == 0) ? dd.x : (q == 1) ? dd.y : (q == 2) ? dd.z : dd.w;
        float s[10] = { ct.x, ct.y, ct.z, nb.x, nb.y, nb.z,
                        ct.x-nb.x, ct.y-nb.y, ct.z-nb.z, d };
        int c2 = 10;
        #pragma unroll
        for (int i = 0; i < 10; i++) {
            a[i] += s[i];
            #pragma unroll
            for (int j2 = i; j2 < 10; j2++) { a[c2] = fmaf(s[i], s[j2], a[c2]); c2++; }
        }
    }
    __shared__ double sacc[65];
    if (tid < 65) sacc[tid] = 0.0;
    __syncthreads();
    #pragma unroll
    for (int v = 0; v < 65; v++) {
        float x = a[v];
        #pragma unroll
        for (int off = 16; off; off >>= 1) x += __shfl_down_sync(0xffffffffu, x, off);
        if ((tid & 31) == 0) atomicAdd(&sacc[v], (double)x);
    }
    __syncthreads();
    if (tid < 65) atomicAdd(&g_msum[tid], sacc[tid]);
}

// ---------------- conv from features (single weight set), BN stats fused --------
__global__ void __launch_bounds__(256) convF_kernel(
    const float* __restrict__ feat,
    const float* __restrict__ W, const float* __restrict__ bias,
    float* __restrict__ y, int CO, int acc_off) {
    __shared__ __align__(16) float Wsh[32*32];
    __shared__ float bsh[32];
    __shared__ float red_s[8][32], red_q[8][32];
    const int oc0 = blockIdx.y << 5;
    for (int t = threadIdx.x; t < 32*32; t += 256) {
        int i = t >> 5, ol = t & 31;
        Wsh[t] = W[(oc0 + ol)*32 + i];
    }
    if (threadIdx.x < 32) bsh[threadIdx.x] = bias[oc0 + threadIdx.x];
    __syncthreads();
    const int p = (blockIdx.x << 8) + threadIdx.x;
    const int b = p >> 13, n = p & (NN-1);
    const int w = threadIdx.x >> 5, lane = threadIdx.x & 31;
    unsigned long long acc2[16];
    #pragma unroll
    for (int o2 = 0; o2 < 16; o2++) acc2[o2] = pack2(bsh[2*o2], bsh[2*o2+1]);
    #pragma unroll 2
    for (int i = 0; i < 32; i++) {
        float x = feat[((b*32 + i) << 13) + n];
        unsigned long long x2 = pack2(x, x);
        const unsigned long long* wr = (const unsigned long long*)&Wsh[i << 5];
        #pragma unroll
        for (int o2 = 0; o2 < 16; o2++) acc2[o2] = ffma2(x2, wr[o2], acc2[o2]);
    }
    float acc[32];
    #pragma unroll
    for (int o2 = 0; o2 < 16; o2++) {
        float2 u = unpack2(acc2[o2]);
        acc[2*o2] = u.x; acc[2*o2+1] = u.y;
    }
    #pragma unroll
    for (int o = 0; o < 32; o++)
        y[((b*CO + oc0 + o) << 13) + n] = acc[o];
    #pragma unroll
    for (int o = 0; o < 32; o++) {
        float v = acc[o], q = v*v;
        #pragma unroll
        for (int off = 16; off; off >>= 1) {
            v += __shfl_xor_sync(0xffffffffu, v, off);
            q += __shfl_xor_sync(0xffffffffu, q, off);
        }
        if (lane == 0) { red_s[w][o] = v; red_q[w][o] = q; }
    }
    __syncthreads();
    if (threadIdx.x < 64) {
        int o = threadIdx.x & 31, which = threadIdx.x >> 5;
        float s = 0.f;
        #pragma unroll
        for (int ww = 0; ww < 8; ww++) s += which ? red_q[ww][o] : red_s[ww][o];
        atomicAdd(which ? &g_csum2[acc_off + oc0 + o] : &g_csum[acc_off + oc0 + o], (double)s);
    }
}

// ---------------- 1x1 conv (CI inputs), in1 gets in-place BN+act computed from g_csum -------
template<int CI, int CI0>
__global__ void __launch_bounds__(256) convB_kernel(
    const float* __restrict__ in0, const float* __restrict__ in1,
    const float* __restrict__ W,   const float* __restrict__ bias,
    const float* __restrict__ gprm, const float* __restrict__ btprm,
    int prm_off, float slope,
    float* __restrict__ y, int CO, int acc_off) {
    __shared__ __align__(16) float Wsh[CI*32];
    __shared__ float bsh[32];
    __shared__ float scsh[CI-CI0], shsh[CI-CI0];
    __shared__ float red_s[8][32], red_q[8][32];
    const int oc0 = blockIdx.y << 5;
    for (int t = threadIdx.x; t < CI*32; t += 256) {
        int i = t >> 5, ol = t & 31;
        Wsh[t] = W[(oc0 + ol)*CI + i];
    }
    if (threadIdx.x < 32) bsh[threadIdx.x] = bias[oc0 + threadIdx.x];
    if (threadIdx.x < (CI-CI0)) {
        int i = threadIdx.x;
        const double P = (double)(BB*NN);
        double mean = g_csum[prm_off + i] / P;
        double var  = g_csum2[prm_off + i] / P - mean*mean;
        double scl  = (double)gprm[i] / sqrt(var + 1e-5);
        scsh[i] = (float)scl;
        shsh[i] = (float)((double)btprm[i] - mean*scl);
    }
    __syncthreads();
    const int p = (blockIdx.x << 8) + threadIdx.x;
    const int b = p >> 13, n = p & (NN-1);
    const int w = threadIdx.x >> 5, lane = threadIdx.x & 31;
    unsigned long long acc2[16];
    #pragma unroll
    for (int o2 = 0; o2 < 16; o2++) acc2[o2] = pack2(bsh[2*o2], bsh[2*o2+1]);
    #pragma unroll 2
    for (int i = 0; i < CI0; i++) {
        float x = in0[((b*CI0 + i) << 13) + n];
        unsigned long long x2 = pack2(x, x);
        const unsigned long long* wr = (const unsigned long long*)&Wsh[i << 5];
        #pragma unroll
        for (int o2 = 0; o2 < 16; o2++) acc2[o2] = ffma2(x2, wr[o2], acc2[o2]);
    }
    #pragma unroll 2
    for (int i = 0; i < CI - CI0; i++) {
        float x = in1[((b*(CI-CI0) + i) << 13) + n];
        x = fmaf(x, scsh[i], shsh[i]);
        x = x > 0.f ? x : slope * x;
        unsigned long long x2 = pack2(x, x);
        const unsigned long long* wr = (const unsigned long long*)&Wsh[(CI0 + i) << 5];
        #pragma unroll
        for (int o2 = 0; o2 < 16; o2++) acc2[o2] = ffma2(x2, wr[o2], acc2[o2]);
    }
    float acc[32];
    #pragma unroll
    for (int o2 = 0; o2 < 16; o2++) {
        float2 u = unpack2(acc2[o2]);
        acc[2*o2] = u.x; acc[2*o2+1] = u.y;
    }
    #pragma unroll
    for (int o = 0; o < 32; o++)
        y[((b*CO + oc0 + o) << 13) + n] = acc[o];
    #pragma unroll
    for (int o = 0; o < 32; o++) {
        float v = acc[o], q = v*v;
        #pragma unroll
        for (int off = 16; off; off >>= 1) {
            v += __shfl_xor_sync(0xffffffffu, v, off);
            q += __shfl_xor_sync(0xffffffffu, q, off);
        }
        if (lane == 0) { red_s[w][o] = v; red_q[w][o] = q; }
    }
    __syncthreads();
    if (threadIdx.x < 64) {
        int o = threadIdx.x & 31, which = threadIdx.x >> 5;
        float s = 0.f;
        #pragma unroll
        for (int ww = 0; ww < 8; ww++) s += which ? red_q[ww][o] : red_s[ww][o];
        atomicAdd(which ? &g_csum2[acc_off + oc0 + o] : &g_csum[acc_off + oc0 + o], (double)s);
    }
}

// ---------------- fused LSE + attentive pool, PPW points/warp, BN-finalize in prologue -----
// h stored in smem pre-packed as f32x2 (u64) pairs: phase-3 does zero packs. (R10-proven)
template<int C, int WARPS, int PPW>
__global__ void __launch_bounds__(WARPS*32) lse_pool_kernel(
    const float* __restrict__ Wl,  const float* __restrict__ bl,
    const float* __restrict__ lg,  const float* __restrict__ lbt,
    const float* __restrict__ Wp,  float* __restrict__ pooled) {
    constexpr int CPT = C / 32;
    constexpr int NT  = WARPS * 32;
    __shared__ float wl_sh[10 * C];
    __shared__ float wp_sh[C * C];
    __shared__ float prm_sh[3 * C];
    __shared__ float Cvs[10][10];
    __shared__ float mmf[10];
    __shared__ __align__(16) float s_sh[WARPS][16][12];
    __shared__ __align__(16) unsigned long long h_sh[WARPS][C][10];  // 8 used + pad

    const int tid = threadIdx.x;
    for (int t = tid; t < 10*C; t += NT) { int i = t / C, c = t % C; wl_sh[t] = Wl[c*10 + i]; }
    for (int t = tid; t < C*C;  t += NT) { int c = t / C, o = t % C; wp_sh[t] = Wp[o*(2*C) + c]; }
    const double P = (double)BB * NN * KK;
    if (tid < 10) mmf[tid] = (float)(g_msum[tid] / P);
    if (tid < 100) {
        int i = tid/10, j = tid%10;
        if (j >= i) {
            int off = 10 + i*10 - (i*(i-1))/2 + (j - i);
            float c = (float)(g_msum[off]/P - (g_msum[i]/P)*(g_msum[j]/P));
            Cvs[i][j] = c; Cvs[j][i] = c;
        }
    }
    __syncthreads();
    if (tid < C) {
        int o = tid;
        float wv[10];
        #pragma unroll
        for (int i = 0; i < 10; i++) wv[i] = wl_sh[i*C + o];
        float mean = bl[o];
        #pragma unroll
        for (int i = 0; i < 10; i++) mean = fmaf(wv[i], mmf[i], mean);
        float var = 0.f;
        #pragma unroll
        for (int i = 0; i < 10; i++) {
            float t = 0.f;
            #pragma unroll
            for (int j = 0; j < 10; j++) t = fmaf(wv[j], Cvs[i][j], t);
            var = fmaf(wv[i], t, var);
        }
        float scl = lg[o] / sqrtf(var + 1e-5f);
        prm_sh[o]       = bl[o];
        prm_sh[C + o]   = scl;
        prm_sh[2*C + o] = lbt[o] - mean*scl;
    }
    __syncthreads();

    const int w = tid >> 5, lane = tid & 31;

    float wlr[CPT][10], br[CPT], scr[CPT], shr[CPT];
    #pragma unroll
    for (int cc = 0; cc < CPT; cc++) {
        int c = lane + 32*cc;
        #pragma unroll
        for (int i = 0; i < 10; i++) wlr[cc][i] = wl_sh[i*C + c];
        br[cc] = prm_sh[c]; scr[cc] = prm_sh[C + c]; shr[cc] = prm_sh[2*C + c];
    }

    #pragma unroll 1
    for (int pp = 0; pp < PPW; pp++) {
        const int pt = (blockIdx.x * WARPS + w) * PPW + pp;
        const int b  = pt >> 13;
        const int n  = pt & (NN-1);

        if (lane < 16) {
            int gofs = (pt << 4) | lane;
            int j    = g_idx[gofs];
            float d  = g_dist[gofs];
            float4 ct = g_cpack[pt];
            float4 nb = g_cpack[(b << 13) + j];
            float* sr = s_sh[w][lane];
            sr[0]=ct.x; sr[1]=ct.y; sr[2]=ct.z;
            sr[3]=nb.x; sr[4]=nb.y; sr[5]=nb.z;
            sr[6]=ct.x-nb.x; sr[7]=ct.y-nb.y; sr[8]=ct.z-nb.z;
            sr[9]=d; sr[10]=0.f; sr[11]=0.f;
        }
        __syncwarp();

        // phase 2: h in registers, store pre-packed u64 pairs (4x STS.128)
        float hreg[CPT][16];
        #pragma unroll
        for (int k = 0; k < 16; k++) {
            const float4* sp = (const float4*)s_sh[w][k];
            float4 a0 = sp[0], a1 = sp[1], a2 = sp[2];
            float sv[10] = { a0.x,a0.y,a0.z,a0.w, a1.x,a1.y,a1.z,a1.w, a2.x,a2.y };
            #pragma unroll
            for (int cc = 0; cc < CPT; cc++) {
                float yv = br[cc];
                #pragma unroll
                for (int i = 0; i < 10; i++) yv = fmaf(wlr[cc][i], sv[i], yv);
                hreg[cc][k] = fmaxf(fmaf(yv, scr[cc], shr[cc]), 0.f);
            }
        }
        #pragma unroll
        for (int cc = 0; cc < CPT; cc++) {
            ulonglong2* dst = (ulonglong2*)&h_sh[w][lane + 32*cc][0];
            dst[0] = make_ulonglong2(pack2(hreg[cc][0],  hreg[cc][1]),
                                     pack2(hreg[cc][2],  hreg[cc][3]));
            dst[1] = make_ulonglong2(pack2(hreg[cc][4],  hreg[cc][5]),
                                     pack2(hreg[cc][6],  hreg[cc][7]));
            dst[2] = make_ulonglong2(pack2(hreg[cc][8],  hreg[cc][9]),
                                     pack2(hreg[cc][10], hreg[cc][11]));
            dst[3] = make_ulonglong2(pack2(hreg[cc][12], hreg[cc][13]),
                                     pack2(hreg[cc][14], hreg[cc][15]));
        }
        __syncwarp();

        // phase 3: score GEMM, packed operands straight from smem
        unsigned long long acc2[CPT][8];
        #pragma unroll
        for (int cc = 0; cc < CPT; cc++)
            #pragma unroll
            for (int k2 = 0; k2 < 8; k2++) acc2[cc][k2] = 0ULL;

        #pragma unroll 4
        for (int c = 0; c < C; c++) {
            const ulonglong2* hp = (const ulonglong2*)&h_sh[w][c][0];
            ulonglong2 A = hp[0], Bq = hp[1], Cq = hp[2], D = hp[3];
            unsigned long long hv2[8] = { A.x, A.y, Bq.x, Bq.y, Cq.x, Cq.y, D.x, D.y };
            #pragma unroll
            for (int cc = 0; cc < CPT; cc++) {
                float wv = wp_sh[c*C + lane + 32*cc];
                unsigned long long w2 = pack2(wv, wv);
                #pragma unroll
                for (int k2 = 0; k2 < 8; k2++) acc2[cc][k2] = ffma2(w2, hv2[k2], acc2[cc][k2]);
            }
        }

        // phase 4: softmax over K + weighted sum (h from registers)
        #pragma unroll
        for (int cc = 0; cc < CPT; cc++) {
            int o = lane + 32*cc;
            float acc[16];
            #pragma unroll
            for (int k2 = 0; k2 < 8; k2++) {
                float2 u = unpack2(acc2[cc][k2]);
                acc[2*k2] = u.x; acc[2*k2+1] = u.y;
            }
            float m = acc[0];
            #pragma unroll
            for (int k = 1; k < 16; k++) m = fmaxf(m, acc[k]);
            float se = 0.f;
            #pragma unroll
            for (int k = 0; k < 16; k++) { acc[k] = __expf(acc[k] - m); se += acc[k]; }
            float sum = 0.f;
            #pragma unroll
            for (int k = 0; k < 16; k++) sum = fmaf(acc[k], hreg[cc][k], sum);
            pooled[((b*C + o) << 13) + n] = sum / se;
        }
        __syncwarp();
    }
}

// ---------------- final: BN params in-block, BN+ReLU+concat, grid-stride float4 ----
__global__ void __launch_bounds__(256) final_kernel(
    const float* __restrict__ gm, const float* __restrict__ btm,
    const float* __restrict__ gr, const float* __restrict__ btr,
    float4* __restrict__ out) {
    __shared__ float scm[128], shm[128], scr_[128], shr_[128];
    const double P = (double)(BB*NN);
    {
        int t = threadIdx.x;
        int off = (t < 128) ? 96 : 224;
        int o   = t & 127;
        double mean = g_csum[off + o] / P;
        double var  = g_csum2[off + o] / P - mean*mean;
        const float* gg = (t < 128) ? gm : gr;
        const float* bb = (t < 128) ? btm : btr;
        double scl = (double)gg[o] / sqrt(var + 1e-5);
        if (t < 128) { scm[o] = (float)scl; shm[o] = (float)((double)bb[o] - mean*scl); }
        else         { scr_[o] = (float)scl; shr_[o] = (float)((double)bb[o] - mean*scl); }
    }
    __syncthreads();
    const int total = BB*256*NN/4;
    for (int t = (blockIdx.x << 8) + threadIdx.x; t < total; t += 512*256) {
        int base = t << 2;
        int b  = base >> 21;
        int r  = base & ((1 << 21) - 1);
        int ch = r >> 13;
        int n  = r & (NN-1);
        float4 v; float sc, sh;
        if (ch < 128) {
            v = *(const float4*)&g_ymain[((b*128 + ch) << 13) + n];
            sc = scm[ch]; sh = shm[ch];
        } else {
            int c = ch - 128;
            v = *(const float4*)&g_yres[((b*128 + c) << 13) + n];
            sc = scr_[c]; sh = shr_[c];
        }
        v.x = fmaxf(fmaf(v.x, sc, sh), 0.f);
        v.y = fmaxf(fmaf(v.y, sc, sh), 0.f);
        v.z = fmaxf(fmaf(v.z, sc, sh), 0.f);
        v.w = fmaxf(fmaf(v.w, sc, sh), 0.f);
        out[t] = v;
    }
}

// ---------------- launch ----------------
extern "C" void kernel_launch(void* const* d_in, const int* in_sizes, int n_in,
                              void* d_out, int out_size) {
    const float* coords   = (const float*)d_in[0];
    const float* features = (const float*)d_in[1];
    const float* mlp1_w  = (const float*)d_in[2];
    const float* mlp1_b  = (const float*)d_in[3];
    const float* mlp1_g  = (const float*)d_in[4];
    const float* mlp1_bt = (const float*)d_in[5];
    const float* lse1_w  = (const float*)d_in[6];
    const float* lse1_b  = (const float*)d_in[7];
    const float* lse1_g  = (const float*)d_in[8];
    const float* lse1_bt = (const float*)d_in[9];
    const float* mlpp1_w  = (const float*)d_in[10];
    const float* mlpp1_b  = (const float*)d_in[11];
    const float* mlpp1_g  = (const float*)d_in[12];
    const float* mlpp1_bt = (const float*)d_in[13];
    const float* lse2_w  = (const float*)d_in[14];
    const float* lse2_b  = (const float*)d_in[15];
    const float* lse2_g  = (const float*)d_in[16];
    const float* lse2_bt = (const float*)d_in[17];
    const float* mlp2_w  = (const float*)d_in[18];
    const float* mlp2_b  = (const float*)d_in[19];
    const float* mlp2_g  = (const float*)d_in[20];
    const float* mlp2_bt = (const float*)d_in[21];
    const float* res_w  = (const float*)d_in[22];
    const float* res_b  = (const float*)d_in[23];
    const float* res_g  = (const float*)d_in[24];
    const float* res_bt = (const float*)d_in[25];
    const float* pool1_w = (const float*)d_in[26];
    const float* pool2_w = (const float*)d_in[28];
    float* out = (float*)d_out;

    void *p_y1, *p_pool1, *p_y2, *p_pool2, *p_ymain, *p_yres;
    cudaGetSymbolAddress(&p_y1, g_y1);       cudaGetSymbolAddress(&p_pool1, g_pool1);
    cudaGetSymbolAddress(&p_y2, g_y2);       cudaGetSymbolAddress(&p_pool2, g_pool2);
    cudaGetSymbolAddress(&p_ymain, g_ymain); cudaGetSymbolAddress(&p_yres, g_yres);

    static bool attr_done = false;
    if (!attr_done) {
        cudaFuncSetAttribute(knn_kernel, cudaFuncAttributeMaxDynamicSharedMemorySize, 73728);
        attr_done = true;
    }

    // 1) pack (zeros accumulators)
    pack_kernel<<<64, 256>>>(coords);
    // 2) mlp1 conv from features
    convF_kernel<<<dim3(64,2), 256>>>(features, mlp1_w, mlp1_b, (float*)p_y1, 64, 0);
    // 3) res conv from features
    convF_kernel<<<dim3(64,4), 256>>>(features, res_w, res_b, (float*)p_yres, 128, 224);
    // 4) knn (96-slot queue)
    knn_kernel<<<256, 512, 73728>>>();
    // 5) spatial moments (batched loads, 256x256)
    moments_kernel<<<256, 256>>>();
    // 6) lse1 + pool1 (PPW=8)
    lse_pool_kernel<64,4,8><<<512, 128>>>(lse1_w, lse1_b, lse1_g, lse1_bt,
                                          pool1_w, (float*)p_pool1);
    // 7) mlpp1
    convB_kernel<128,64><<<dim3(64,1), 256>>>((float*)p_pool1, (float*)p_y1, mlpp1_w, mlpp1_b,
                                              mlp1_g, mlp1_bt, 0, 0.2f, (float*)p_y2, 32, 64);
    // 8) lse2 + pool2 (PPW=8)
    lse_pool_kernel<32,8,8><<<256, 256>>>(lse2_w, lse2_b, lse2_g, lse2_bt,
                                          pool2_w, (float*)p_pool2);
    // 9) mlp2
    convB_kernel<64,32><<<dim3(64,4), 256>>>((float*)p_pool2, (float*)p_y2, mlp2_w, mlp2_b,
                                             mlpp1_g, mlpp1_bt, 64, 0.0f, (float*)p_ymain, 128, 96);
    // 10) final
    final_kernel<<<512, 256>>>(mlp2_g, mlp2_bt, res_g, res_bt, (float4*)out);
}

// round 17
// speedup vs baseline: 1.2268x; 1.0453x over previous
#include <cuda_runtime.h>
#include <math.h>
#include <stdint.h>

#define BB 2
#define NN 8192
#define KK 16

// ---------------- f32x2 packed-math helpers (sm_100+ PTX) ----------------
__device__ __forceinline__ unsigned long long ffma2(unsigned long long a, unsigned long long b,
                                                    unsigned long long c) {
    unsigned long long d;
    asm("fma.rn.f32x2 %0, %1, %2, %3;" : "=l"(d) : "l"(a), "l"(b), "l"(c));
    return d;
}
__device__ __forceinline__ unsigned long long pack2(float x, float y) {
    unsigned long long d;
    asm("mov.b64 %0, {%1, %2};" : "=l"(d) : "f"(x), "f"(y));
    return d;
}
__device__ __forceinline__ float2 unpack2(unsigned long long v) {
    float2 r;
    asm("mov.b64 {%0, %1}, %2;" : "=f"(r.x), "=f"(r.y) : "l"(v));
    return r;
}

// ---------------- scratch (static device globals; no allocation) ----------------
__device__ __align__(16) float4 g_cpack[BB*NN];   // raw coords + |c|^2
__device__ __align__(16) float4 g_cneg [BB*NN];   // (-2x,-2y,-2z, |c|^2) for KNN
__device__ __align__(16) int    g_idx [BB*NN*KK];
__device__ __align__(16) float  g_dist[BB*NN*KK];
__device__ __align__(16) float  g_y1   [BB*64 *NN];
__device__ __align__(16) float  g_pool1[BB*64 *NN];
__device__ __align__(16) float  g_y2   [BB*32 *NN];
__device__ __align__(16) float  g_pool2[BB*32 *NN];
__device__ __align__(16) float  g_ymain[BB*128*NN];
__device__ __align__(16) float  g_yres [BB*128*NN];
__device__ double g_msum[65];
__device__ double g_csum [352];   // [0,64)=mlp1 [64,96)=mlpp1 [96,224)=mlp2 [224,352)=res
__device__ double g_csum2[352];

// ---------------- pack coords + squared norm; zero accumulators ----------------
__global__ void __launch_bounds__(256) pack_kernel(const float* __restrict__ coords) {
    int p = (blockIdx.x << 8) + threadIdx.x;          // < BB*NN
    float x = coords[p*3+0], y = coords[p*3+1], z = coords[p*3+2];
    float w = fmaf(x, x, fmaf(y, y, z*z));
    g_cpack[p] = make_float4(x, y, z, w);
    g_cneg[p]  = make_float4(-2.f*x, -2.f*y, -2.f*z, w);
    if (p < 352) { g_csum[p] = 0.0; g_csum2[p] = 0.0; }
    if (p < 65)  g_msum[p] = 0.0;
}

// ---------------- KNN v7 (R16-proven): 4 queries/warp, 96-slot queue + pivot-shrink --------
__device__ __forceinline__ float knn_exact16(float* qd, int* qi, float* td, int* ti,
                                             int lane, int& cnt) {
    const float INF = __int_as_float(0x7f800000);
    for (int s = cnt + lane; s < 96; s += 32) qd[s] = INF;
    __syncwarp();
    #pragma unroll 1
    for (int r = 0; r < 16; r++) {
        unsigned u  = __float_as_uint(qd[lane]);      int p = lane;
        unsigned u1 = __float_as_uint(qd[lane + 32]);
        unsigned u2 = __float_as_uint(qd[lane + 64]);
        if (u1 < u) { u = u1; p = lane + 32; }
        if (u2 < u) { u = u2; p = lane + 64; }
        unsigned m  = __reduce_min_sync(0xffffffffu, u);
        unsigned z  = (u == m) ? (unsigned)p : 0xFFFFu;
        unsigned pm = __reduce_min_sync(0xffffffffu, z);
        if (lane == 0) {
            td[r] = __uint_as_float(m);
            ti[r] = qi[pm];
            qd[pm] = INF;
        }
        __syncwarp();
    }
    cnt = 0;
    __syncwarp();
    return td[15];
}

__device__ __forceinline__ float knn_shrink(float* qd, int* qi, float* td, int* ti,
                                            int lane, const unsigned lt, int& cnt) {
    const float INF = __int_as_float(0x7f800000);
    for (int s = cnt + lane; s < 96; s += 32) qd[s] = INF;
    __syncwarp();
    float v0 = qd[lane], v1 = qd[lane + 32], v2 = qd[lane + 64];
    float mn = fminf(fminf(v0, v1), v2);
    float mx = fmaxf(fmaxf(v0 < INF ? v0 : -INF, v1 < INF ? v1 : -INF),
                     (v2 < INF ? v2 : -INF));
    #pragma unroll
    for (int off = 16; off; off >>= 1) {
        mn = fminf(mn, __shfl_xor_sync(0xffffffffu, mn, off));
        mx = fmaxf(mx, __shfl_xor_sync(0xffffffffu, mx, off));
    }
    float lo = mn, hi = mx;
    int hc = cnt;
    #pragma unroll 1
    for (int it = 0; it < 14 && hc > 48; it++) {
        float mid = 0.5f * (lo + hi);
        if (!(mid > lo) || !(mid < hi)) break;
        int c = (int)(v0 <= mid) + (int)(v1 <= mid) + (int)(v2 <= mid);
        c = (int)__reduce_add_sync(0xffffffffu, (unsigned)c);
        if (c >= 16) { hi = mid; hc = c; } else lo = mid;
    }
    if (hc > 64) {                          // can't bisect below (duplicates): exact reset
        float tau = knn_exact16(qd, qi, td, ti, lane, cnt);
        if (lane < 16) { qd[lane] = td[lane]; qi[lane] = ti[lane]; }
        cnt = 16;
        __syncwarp();
        return tau;
    }
    int nc = 0;
    #pragma unroll
    for (int g = 0; g < 3; g++) {
        float v = (g == 0) ? v0 : (g == 1) ? v1 : v2;
        int idx = qi[lane + (g << 5)];
        bool keep = v <= hi;
        unsigned m = __ballot_sync(0xffffffffu, keep);
        if (keep) {
            int pos = nc + __popc(m & lt);
            qd[pos] = v;
            qi[pos] = idx;
        }
        nc += __popc(m);
    }
    cnt = nc;
    __syncwarp();
    return hi;
}

__global__ void __launch_bounds__(512, 2) knn_kernel() {
    extern __shared__ char dyn[];
    float4* tile = (float4*)dyn;                       // 1024*16 = 16384
    float*  qds  = (float*)(dyn + 16384);              // 64*96*4 = 24576
    int*    qis  = (int*)  (dyn + 40960);              // 24576
    float*  tds  = (float*)(dyn + 65536);              // 4096
    int*    tis  = (int*)  (dyn + 69632);              // 4096  (total 73728)

    const float INF = __int_as_float(0x7f800000);
    const int tid = threadIdx.x, w = tid >> 5, lane = tid & 31;
    const int b     = blockIdx.x >> 7;
    const int qbase = ((blockIdx.x & 127) << 6) | (w << 2);
    const int qslot = w << 2;
    const unsigned lt = (1u << lane) - 1u;

    float* qd0 = qds + (qslot+0)*96; int* qi0 = qis + (qslot+0)*96;
    float* qd1 = qds + (qslot+1)*96; int* qi1 = qis + (qslot+1)*96;
    float* qd2 = qds + (qslot+2)*96; int* qi2 = qis + (qslot+2)*96;
    float* qd3 = qds + (qslot+3)*96; int* qi3 = qis + (qslot+3)*96;
    float* td0 = tds + ((qslot+0) << 4); int* ti0 = tis + ((qslot+0) << 4);
    float* td1 = tds + ((qslot+1) << 4); int* ti1 = tis + ((qslot+1) << 4);
    float* td2 = tds + ((qslot+2) << 4); int* ti2 = tis + ((qslot+2) << 4);
    float* td3 = tds + ((qslot+3) << 4); int* ti3 = tis + ((qslot+3) << 4);

    const float4 q0 = g_cpack[(b << 13) + qbase + 0];
    const float4 q1 = g_cpack[(b << 13) + qbase + 1];
    const float4 q2 = g_cpack[(b << 13) + qbase + 2];
    const float4 q3 = g_cpack[(b << 13) + qbase + 3];
    const int n0 = qbase, n1 = qbase+1, n2 = qbase+2, n3 = qbase+3;
    float t0 = INF, t1 = INF, t2 = INF, t3 = INF;
    int c0 = 0, c1 = 0, c2 = 0, c3 = 0;

    for (int t = 0; t < 8; t++) {
        __syncthreads();
        tile[tid]       = g_cneg[(b << 13) + (t << 10) + tid];
        tile[tid + 512] = g_cneg[(b << 13) + (t << 10) + tid + 512];
        __syncthreads();
        const int jb = t << 10;
        #pragma unroll 1
        for (int s = 0; s < 32; s++) {
            float4 cc = tile[(s << 5) + lane];
            int j = jb + (s << 5) + lane;
            float e0 = fmaf(cc.x, q0.x, fmaf(cc.y, q0.y, fmaf(cc.z, q0.z, cc.w)));
            float e1 = fmaf(cc.x, q1.x, fmaf(cc.y, q1.y, fmaf(cc.z, q1.z, cc.w)));
            float e2 = fmaf(cc.x, q2.x, fmaf(cc.y, q2.y, fmaf(cc.z, q2.z, cc.w)));
            float e3 = fmaf(cc.x, q3.x, fmaf(cc.y, q3.y, fmaf(cc.z, q3.z, cc.w)));
            bool p0 = e0 < t0, p1 = e1 < t1, p2 = e2 < t2, p3 = e3 < t3;
            if (__ballot_sync(0xffffffffu, p0 | p1 | p2 | p3)) {
                unsigned m;
                #define KNN_PROC(P, E, QW, NQ, QD, QI, TD, TI, CN, TH)                      \
                    m = __ballot_sync(0xffffffffu, P);                                      \
                    if (m) {                                                                \
                        if (P) {                                                            \
                            int pos = CN + __popc(m & lt);                                  \
                            QD[pos] = (j == NQ) ? INF : fmaxf(E + QW, 0.f);                 \
                            QI[pos] = j;                                                    \
                        }                                                                   \
                        CN += __popc(m);                                                    \
                        if (CN > 64) TH = knn_shrink(QD, QI, TD, TI, lane, lt, CN) - QW;    \
                    }
                KNN_PROC(p0, e0, q0.w, n0, qd0, qi0, td0, ti0, c0, t0)
                KNN_PROC(p1, e1, q1.w, n1, qd1, qi1, td1, ti1, c1, t1)
                KNN_PROC(p2, e2, q2.w, n2, qd2, qi2, td2, ti2, c2, t2)
                KNN_PROC(p3, e3, q3.w, n3, qd3, qi3, td3, ti3, c3, t3)
                #undef KNN_PROC
            }
        }
    }
    knn_exact16(qd0, qi0, td0, ti0, lane, c0);
    knn_exact16(qd1, qi1, td1, ti1, lane, c1);
    knn_exact16(qd2, qi2, td2, ti2, lane, c2);
    knn_exact16(qd3, qi3, td3, ti3, lane, c3);

    if (lane < 16) {
        int base = ((b << 13) + qbase) << 4;
        g_idx [base + lane]      = ti0[lane];
        g_dist[base + lane]      = td0[lane];
        g_idx [base + 16 + lane] = ti1[lane];
        g_dist[base + 16 + lane] = td1[lane];
        g_idx [base + 32 + lane] = ti2[lane];
        g_dist[base + 32 + lane] = td2[lane];
        g_idx [base + 48 + lane] = ti3[lane];
        g_dist[base + 48 + lane] = td3[lane];
    }
}

// ---------------- spatial moments: xor-reduce + smem float matrix (no smem f64 atomics) ----
__global__ void __launch_bounds__(256) moments_kernel() {
    const int tid = threadIdx.x, wrp = tid >> 5, lane = tid & 31;
    const int p0  = (((blockIdx.x << 8) + tid) << 2);  // grid 256: covers BB*NN*KK
    const int bn  = p0 >> 4;
    const int b   = bn >> 13;
    int4   jj = *(const int4*)&g_idx[p0];
    float4 dd = *(const float4*)&g_dist[p0];
    float4 ct = g_cpack[bn];
    float4 nb0 = g_cpack[(b << 13) + jj.x];
    float4 nb1 = g_cpack[(b << 13) + jj.y];
    float4 nb2 = g_cpack[(b << 13) + jj.z];
    float4 nb3 = g_cpack[(b << 13) + jj.w];

    float a[65];
    #pragma unroll
    for (int v = 0; v < 65; v++) a[v] = 0.f;
    #pragma unroll
    for (int q = 0; q < 4; q++) {
        float4 nb = (q == 0) ? nb0 : (q == 1) ? nb1 : (q == 2) ? nb2 : nb3;
        float d   = (q == 0) ? dd.x : (q == 1) ? dd.y : (q == 2) ? dd.z : dd.w;
        float s[10] = { ct.x, ct.y, ct.z, nb.x, nb.y, nb.z,
                        ct.x-nb.x, ct.y-nb.y, ct.z-nb.z, d };
        int c2 = 10;
        #pragma unroll
        for (int i = 0; i < 10; i++) {
            a[i] += s[i];
            #pragma unroll
            for (int j2 = i; j2 < 10; j2++) { a[c2] = fmaf(s[i], s[j2], a[c2]); c2++; }
        }
    }
    __shared__ float sred[8][65];
    // xor butterfly: every lane ends holding the warp total for each v
    #pragma unroll
    for (int v = 0; v < 65; v++) {
        float x = a[v];
        #pragma unroll
        for (int off = 16; off; off >>= 1) x += __shfl_xor_sync(0xffffffffu, x, off);
        a[v] = x;
    }
    sred[wrp][lane] = a[lane];
    sred[wrp][lane + 32] = a[lane + 32];
    if (lane == 0) sred[wrp][64] = a[64];
    __syncthreads();
    if (tid < 65) {
        float s = 0.f;
        #pragma unroll
        for (int ww = 0; ww < 8; ww++) s += sred[ww][tid];
        atomicAdd(&g_msum[tid], (double)s);
    }
}

// ---------------- conv from features (single weight set), BN stats fused --------
__global__ void __launch_bounds__(256) convF_kernel(
    const float* __restrict__ feat,
    const float* __restrict__ W, const float* __restrict__ bias,
    float* __restrict__ y, int CO, int acc_off) {
    __shared__ __align__(16) float Wsh[32*32];
    __shared__ float bsh[32];
    __shared__ float red_s[8][32], red_q[8][32];
    const int oc0 = blockIdx.y << 5;
    for (int t = threadIdx.x; t < 32*32; t += 256) {
        int i = t >> 5, ol = t & 31;
        Wsh[t] = W[(oc0 + ol)*32 + i];
    }
    if (threadIdx.x < 32) bsh[threadIdx.x] = bias[oc0 + threadIdx.x];
    __syncthreads();
    const int p = (blockIdx.x << 8) + threadIdx.x;
    const int b = p >> 13, n = p & (NN-1);
    const int w = threadIdx.x >> 5, lane = threadIdx.x & 31;
    unsigned long long acc2[16];
    #pragma unroll
    for (int o2 = 0; o2 < 16; o2++) acc2[o2] = pack2(bsh[2*o2], bsh[2*o2+1]);
    #pragma unroll 2
    for (int i = 0; i < 32; i++) {
        float x = feat[((b*32 + i) << 13) + n];
        unsigned long long x2 = pack2(x, x);
        const unsigned long long* wr = (const unsigned long long*)&Wsh[i << 5];
        #pragma unroll
        for (int o2 = 0; o2 < 16; o2++) acc2[o2] = ffma2(x2, wr[o2], acc2[o2]);
    }
    float acc[32];
    #pragma unroll
    for (int o2 = 0; o2 < 16; o2++) {
        float2 u = unpack2(acc2[o2]);
        acc[2*o2] = u.x; acc[2*o2+1] = u.y;
    }
    #pragma unroll
    for (int o = 0; o < 32; o++)
        y[((b*CO + oc0 + o) << 13) + n] = acc[o];
    #pragma unroll
    for (int o = 0; o < 32; o++) {
        float v = acc[o], q = v*v;
        #pragma unroll
        for (int off = 16; off; off >>= 1) {
            v += __shfl_xor_sync(0xffffffffu, v, off);
            q += __shfl_xor_sync(0xffffffffu, q, off);
        }
        if (lane == 0) { red_s[w][o] = v; red_q[w][o] = q; }
    }
    __syncthreads();
    if (threadIdx.x < 64) {
        int o = threadIdx.x & 31, which = threadIdx.x >> 5;
        float s = 0.f;
        #pragma unroll
        for (int ww = 0; ww < 8; ww++) s += which ? red_q[ww][o] : red_s[ww][o];
        atomicAdd(which ? &g_csum2[acc_off + oc0 + o] : &g_csum[acc_off + oc0 + o], (double)s);
    }
}

// ---------------- 1x1 conv (CI inputs), in1 gets in-place BN+act computed from g_csum -------
template<int CI, int CI0>
__global__ void __launch_bounds__(256) convB_kernel(
    const float* __restrict__ in0, const float* __restrict__ in1,
    const float* __restrict__ W,   const float* __restrict__ bias,
    const float* __restrict__ gprm, const float* __restrict__ btprm,
    int prm_off, float slope,
    float* __restrict__ y, int CO, int acc_off) {
    __shared__ __align__(16) float Wsh[CI*32];
    __shared__ float bsh[32];
    __shared__ float scsh[CI-CI0], shsh[CI-CI0];
    __shared__ float red_s[8][32], red_q[8][32];
    const int oc0 = blockIdx.y << 5;
    for (int t = threadIdx.x; t < CI*32; t += 256) {
        int i = t >> 5, ol = t & 31;
        Wsh[t] = W[(oc0 + ol)*CI + i];
    }
    if (threadIdx.x < 32) bsh[threadIdx.x] = bias[oc0 + threadIdx.x];
    if (threadIdx.x < (CI-CI0)) {
        int i = threadIdx.x;
        const double P = (double)(BB*NN);
        double mean = g_csum[prm_off + i] / P;
        double var  = g_csum2[prm_off + i] / P - mean*mean;
        double scl  = (double)gprm[i] / sqrt(var + 1e-5);
        scsh[i] = (float)scl;
        shsh[i] = (float)((double)btprm[i] - mean*scl);
    }
    __syncthreads();
    const int p = (blockIdx.x << 8) + threadIdx.x;
    const int b = p >> 13, n = p & (NN-1);
    const int w = threadIdx.x >> 5, lane = threadIdx.x & 31;
    unsigned long long acc2[16];
    #pragma unroll
    for (int o2 = 0; o2 < 16; o2++) acc2[o2] = pack2(bsh[2*o2], bsh[2*o2+1]);
    #pragma unroll 2
    for (int i = 0; i < CI0; i++) {
        float x = in0[((b*CI0 + i) << 13) + n];
        unsigned long long x2 = pack2(x, x);
        const unsigned long long* wr = (const unsigned long long*)&Wsh[i << 5];
        #pragma unroll
        for (int o2 = 0; o2 < 16; o2++) acc2[o2] = ffma2(x2, wr[o2], acc2[o2]);
    }
    #pragma unroll 2
    for (int i = 0; i < CI - CI0; i++) {
        float x = in1[((b*(CI-CI0) + i) << 13) + n];
        x = fmaf(x, scsh[i], shsh[i]);
        x = x > 0.f ? x : slope * x;
        unsigned long long x2 = pack2(x, x);
        const unsigned long long* wr = (const unsigned long long*)&Wsh[(CI0 + i) << 5];
        #pragma unroll
        for (int o2 = 0; o2 < 16; o2++) acc2[o2] = ffma2(x2, wr[o2], acc2[o2]);
    }
    float acc[32];
    #pragma unroll
    for (int o2 = 0; o2 < 16; o2++) {
        float2 u = unpack2(acc2[o2]);
        acc[2*o2] = u.x; acc[2*o2+1] = u.y;
    }
    #pragma unroll
    for (int o = 0; o < 32; o++)
        y[((b*CO + oc0 + o) << 13) + n] = acc[o];
    #pragma unroll
    for (int o = 0; o < 32; o++) {
        float v = acc[o], q = v*v;
        #pragma unroll
        for (int off = 16; off; off >>= 1) {
            v += __shfl_xor_sync(0xffffffffu, v, off);
            q += __shfl_xor_sync(0xffffffffu, q, off);
        }
        if (lane == 0) { red_s[w][o] = v; red_q[w][o] = q; }
    }
    __syncthreads();
    if (threadIdx.x < 64) {
        int o = threadIdx.x & 31, which = threadIdx.x >> 5;
        float s = 0.f;
        #pragma unroll
        for (int ww = 0; ww < 8; ww++) s += which ? red_q[ww][o] : red_s[ww][o];
        atomicAdd(which ? &g_csum2[acc_off + oc0 + o] : &g_csum[acc_off + oc0 + o], (double)s);
    }
}

// ---------------- fused LSE + attentive pool, PPW points/warp, BN-finalize in prologue -----
// phase 2 computes h two-k-at-a-time and stores packed u64 immediately (no hreg array);
// phase 4 re-reads h from smem. Cuts ~32 live registers -> higher occupancy.
template<int C, int WARPS, int PPW>
__global__ void __launch_bounds__(WARPS*32) lse_pool_kernel(
    const float* __restrict__ Wl,  const float* __restrict__ bl,
    const float* __restrict__ lg,  const float* __restrict__ lbt,
    const float* __restrict__ Wp,  float* __restrict__ pooled) {
    constexpr int CPT = C / 32;
    constexpr int NT  = WARPS * 32;
    __shared__ float wl_sh[10 * C];
    __shared__ float wp_sh[C * C];
    __shared__ float prm_sh[3 * C];
    __shared__ float Cvs[10][10];
    __shared__ float mmf[10];
    __shared__ __align__(16) float s_sh[WARPS][16][12];
    __shared__ __align__(16) unsigned long long h_sh[WARPS][C][10];  // 8 used + pad

    const int tid = threadIdx.x;
    for (int t = tid; t < 10*C; t += NT) { int i = t / C, c = t % C; wl_sh[t] = Wl[c*10 + i]; }
    for (int t = tid; t < C*C;  t += NT) { int c = t / C, o = t % C; wp_sh[t] = Wp[o*(2*C) + c]; }
    const double P = (double)BB * NN * KK;
    if (tid < 10) mmf[tid] = (float)(g_msum[tid] / P);
    if (tid < 100) {
        int i = tid/10, j = tid%10;
        if (j >= i) {
            int off = 10 + i*10 - (i*(i-1))/2 + (j - i);
            float c = (float)(g_msum[off]/P - (g_msum[i]/P)*(g_msum[j]/P));
            Cvs[i][j] = c; Cvs[j][i] = c;
        }
    }
    __syncthreads();
    if (tid < C) {
        int o = tid;
        float wv[10];
        #pragma unroll
        for (int i = 0; i < 10; i++) wv[i] = wl_sh[i*C + o];
        float mean = bl[o];
        #pragma unroll
        for (int i = 0; i < 10; i++) mean = fmaf(wv[i], mmf[i], mean);
        float var = 0.f;
        #pragma unroll
        for (int i = 0; i < 10; i++) {
            float t = 0.f;
            #pragma unroll
            for (int j = 0; j < 10; j++) t = fmaf(wv[j], Cvs[i][j], t);
            var = fmaf(wv[i], t, var);
        }
        float scl = lg[o] / sqrtf(var + 1e-5f);
        prm_sh[o]       = bl[o];
        prm_sh[C + o]   = scl;
        prm_sh[2*C + o] = lbt[o] - mean*scl;
    }
    __syncthreads();

    const int w = tid >> 5, lane = tid & 31;

    float wlr[CPT][10], br[CPT], scr[CPT], shr[CPT];
    #pragma unroll
    for (int cc = 0; cc < CPT; cc++) {
        int c = lane + 32*cc;
        #pragma unroll
        for (int i = 0; i < 10; i++) wlr[cc][i] = wl_sh[i*C + c];
        br[cc] = prm_sh[c]; scr[cc] = prm_sh[C + c]; shr[cc] = prm_sh[2*C + c];
    }

    #pragma unroll 1
    for (int pp = 0; pp < PPW; pp++) {
        const int pt = (blockIdx.x * WARPS + w) * PPW + pp;
        const int b  = pt >> 13;
        const int n  = pt & (NN-1);

        if (lane < 16) {
            int gofs = (pt << 4) | lane;
            int j    = g_idx[gofs];
            float d  = g_dist[gofs];
            float4 ct = g_cpack[pt];
            float4 nb = g_cpack[(b << 13) + j];
            float* sr = s_sh[w][lane];
            sr[0]=ct.x; sr[1]=ct.y; sr[2]=ct.z;
            sr[3]=nb.x; sr[4]=nb.y; sr[5]=nb.z;
            sr[6]=ct.x-nb.x; sr[7]=ct.y-nb.y; sr[8]=ct.z-nb.z;
            sr[9]=d; sr[10]=0.f; sr[11]=0.f;
        }
        __syncwarp();

        // phase 2: two k's at a time, store packed u64 immediately
        #pragma unroll
        for (int k2 = 0; k2 < 8; k2++) {
            const float4* spA = (const float4*)s_sh[w][2*k2];
            const float4* spB = (const float4*)s_sh[w][2*k2 + 1];
            float4 A0 = spA[0], A1 = spA[1], A2 = spA[2];
            float4 B0 = spB[0], B1 = spB[1], B2 = spB[2];
            float svA[10] = { A0.x,A0.y,A0.z,A0.w, A1.x,A1.y,A1.z,A1.w, A2.x,A2.y };
            float svB[10] = { B0.x,B0.y,B0.z,B0.w, B1.x,B1.y,B1.z,B1.w, B2.x,B2.y };
            #pragma unroll
            for (int cc = 0; cc < CPT; cc++) {
                float ya = br[cc], yb = br[cc];
                #pragma unroll
                for (int i = 0; i < 10; i++) {
                    ya = fmaf(wlr[cc][i], svA[i], ya);
                    yb = fmaf(wlr[cc][i], svB[i], yb);
                }
                float ha = fmaxf(fmaf(ya, scr[cc], shr[cc]), 0.f);
                float hb = fmaxf(fmaf(yb, scr[cc], shr[cc]), 0.f);
                h_sh[w][lane + 32*cc][k2] = pack2(ha, hb);
            }
        }
        __syncwarp();

        // phase 3: score GEMM, packed operands straight from smem
        unsigned long long acc2[CPT][8];
        #pragma unroll
        for (int cc = 0; cc < CPT; cc++)
            #pragma unroll
            for (int k2 = 0; k2 < 8; k2++) acc2[cc][k2] = 0ULL;

        #pragma unroll 4
        for (int c = 0; c < C; c++) {
            const ulonglong2* hp = (const ulonglong2*)&h_sh[w][c][0];
            ulonglong2 A = hp[0], Bq = hp[1], Cq = hp[2], D = hp[3];
            unsigned long long hv2[8] = { A.x, A.y, Bq.x, Bq.y, Cq.x, Cq.y, D.x, D.y };
            #pragma unroll
            for (int cc = 0; cc < CPT; cc++) {
                float wv = wp_sh[c*C + lane + 32*cc];
                unsigned long long w2 = pack2(wv, wv);
                #pragma unroll
                for (int k2 = 0; k2 < 8; k2++) acc2[cc][k2] = ffma2(w2, hv2[k2], acc2[cc][k2]);
            }
        }

        // phase 4: softmax over K + weighted sum (h re-read from smem)
        #pragma unroll
        for (int cc = 0; cc < CPT; cc++) {
            int o = lane + 32*cc;
            float acc[16];
            #pragma unroll
            for (int k2 = 0; k2 < 8; k2++) {
                float2 u = unpack2(acc2[cc][k2]);
                acc[2*k2] = u.x; acc[2*k2+1] = u.y;
            }
            float m = acc[0];
            #pragma unroll
            for (int k = 1; k < 16; k++) m = fmaxf(m, acc[k]);
            float se = 0.f;
            #pragma unroll
            for (int k = 0; k < 16; k++) { acc[k] = __expf(acc[k] - m); se += acc[k]; }
            const ulonglong2* hpo = (const ulonglong2*)&h_sh[w][o][0];
            ulonglong2 HA = hpo[0], HB = hpo[1], HC = hpo[2], HD = hpo[3];
            unsigned long long hq[8] = { HA.x, HA.y, HB.x, HB.y, HC.x, HC.y, HD.x, HD.y };
            float sum = 0.f;
            #pragma unroll
            for (int k2 = 0; k2 < 8; k2++) {
                float2 u = unpack2(hq[k2]);
                sum = fmaf(acc[2*k2], u.x, sum);
                sum = fmaf(acc[2*k2+1], u.y, sum);
            }
            pooled[((b*C + o) << 13) + n] = sum / se;
        }
        __syncwarp();
    }
}

// ---------------- final: BN params in-block, BN+ReLU+concat, grid-stride float4 ----
__global__ void __launch_bounds__(256) final_kernel(
    const float* __restrict__ gm, const float* __restrict__ btm,
    const float* __restrict__ gr, const float* __restrict__ btr,
    float4* __restrict__ out) {
    __shared__ float scm[128], shm[128], scr_[128], shr_[128];
    const double P = (double)(BB*NN);
    {
        int t = threadIdx.x;
        int off = (t < 128) ? 96 : 224;
        int o   = t & 127;
        double mean = g_csum[off + o] / P;
        double var  = g_csum2[off + o] / P - mean*mean;
        const float* gg = (t < 128) ? gm : gr;
        const float* bb = (t < 128) ? btm : btr;
        double scl = (double)gg[o] / sqrt(var + 1e-5);
        if (t < 128) { scm[o] = (float)scl; shm[o] = (float)((double)bb[o] - mean*scl); }
        else         { scr_[o] = (float)scl; shr_[o] = (float)((double)bb[o] - mean*scl); }
    }
    __syncthreads();
    const int total = BB*256*NN/4;
    for (int t = (blockIdx.x << 8) + threadIdx.x; t < total; t += 512*256) {
        int base = t << 2;
        int b  = base >> 21;
        int r  = base & ((1 << 21) - 1);
        int ch = r >> 13;
        int n  = r & (NN-1);
        float4 v; float sc, sh;
        if (ch < 128) {
            v = *(const float4*)&g_ymain[((b*128 + ch) << 13) + n];
            sc = scm[ch]; sh = shm[ch];
        } else {
            int c = ch - 128;
            v = *(const float4*)&g_yres[((b*128 + c) << 13) + n];
            sc = scr_[c]; sh = shr_[c];
        }
        v.x = fmaxf(fmaf(v.x, sc, sh), 0.f);
        v.y = fmaxf(fmaf(v.y, sc, sh), 0.f);
        v.z = fmaxf(fmaf(v.z, sc, sh), 0.f);
        v.w = fmaxf(fmaf(v.w, sc, sh), 0.f);
        out[t] = v;
    }
}

// ---------------- launch ----------------
extern "C" void kernel_launch(void* const* d_in, const int* in_sizes, int n_in,
                              void* d_out, int out_size) {
    const float* coords   = (const float*)d_in[0];
    const float* features = (const float*)d_in[1];
    const float* mlp1_w  = (const float*)d_in[2];
    const float* mlp1_b  = (const float*)d_in[3];
    const float* mlp1_g  = (const float*)d_in[4];
    const float* mlp1_bt = (const float*)d_in[5];
    const float* lse1_w  = (const float*)d_in[6];
    const float* lse1_b  = (const float*)d_in[7];
    const float* lse1_g  = (const float*)d_in[8];
    const float* lse1_bt = (const float*)d_in[9];
    const float* mlpp1_w  = (const float*)d_in[10];
    const float* mlpp1_b  = (const float*)d_in[11];
    const float* mlpp1_g  = (const float*)d_in[12];
    const float* mlpp1_bt = (const float*)d_in[13];
    const float* lse2_w  = (const float*)d_in[14];
    const float* lse2_b  = (const float*)d_in[15];
    const float* lse2_g  = (const float*)d_in[16];
    const float* lse2_bt = (const float*)d_in[17];
    const float* mlp2_w  = (const float*)d_in[18];
    const float* mlp2_b  = (const float*)d_in[19];
    const float* mlp2_g  = (const float*)d_in[20];
    const float* mlp2_bt = (const float*)d_in[21];
    const float* res_w  = (const float*)d_in[22];
    const float* res_b  = (const float*)d_in[23];
    const float* res_g  = (const float*)d_in[24];
    const float* res_bt = (const float*)d_in[25];
    const float* pool1_w = (const float*)d_in[26];
    const float* pool2_w = (const float*)d_in[28];
    float* out = (float*)d_out;

    void *p_y1, *p_pool1, *p_y2, *p_pool2, *p_ymain, *p_yres;
    cudaGetSymbolAddress(&p_y1, g_y1);       cudaGetSymbolAddress(&p_pool1, g_pool1);
    cudaGetSymbolAddress(&p_y2, g_y2);       cudaGetSymbolAddress(&p_pool2, g_pool2);
    cudaGetSymbolAddress(&p_ymain, g_ymain); cudaGetSymbolAddress(&p_yres, g_yres);

    static bool attr_done = false;
    if (!attr_done) {
        cudaFuncSetAttribute(knn_kernel, cudaFuncAttributeMaxDynamicSharedMemorySize, 73728);
        attr_done = true;
    }

    // 1) pack (zeros accumulators)
    pack_kernel<<<64, 256>>>(coords);
    // 2) mlp1 conv from features
    convF_kernel<<<dim3(64,2), 256>>>(features, mlp1_w, mlp1_b, (float*)p_y1, 64, 0);
    // 3) res conv from features
    convF_kernel<<<dim3(64,4), 256>>>(features, res_w, res_b, (float*)p_yres, 128, 224);
    // 4) knn (96-slot queue)
    knn_kernel<<<256, 512, 73728>>>();
    // 5) spatial moments
    moments_kernel<<<256, 256>>>();
    // 6) lse1 + pool1 (PPW=8)
    lse_pool_kernel<64,4,8><<<512, 128>>>(lse1_w, lse1_b, lse1_g, lse1_bt,
                                          pool1_w, (float*)p_pool1);
    // 7) mlpp1
    convB_kernel<128,64><<<dim3(64,1), 256>>>((float*)p_pool1, (float*)p_y1, mlpp1_w, mlpp1_b,
                                              mlp1_g, mlp1_bt, 0, 0.2f, (float*)p_y2, 32, 64);
    // 8) lse2 + pool2 (PPW=8)
    lse_pool_kernel<32,8,8><<<256, 256>>>(lse2_w, lse2_b, lse2_g, lse2_bt,
                                          pool2_w, (float*)p_pool2);
    // 9) mlp2
    convB_kernel<64,32><<<dim3(64,4), 256>>>((float*)p_pool2, (float*)p_y2, mlp2_w, mlp2_b,
                                             mlpp1_g, mlpp1_bt, 64, 0.0f, (float*)p_ymain, 128, 96);
    // 10) final
    final_kernel<<<512, 256>>>(mlp2_g, mlp2_bt, res_g, res_bt, (float4*)out);
}